// round 14
// baseline (speedup 1.0000x reference)
#include <cuda_runtime.h>
#include <cstdint>

// R13 == R12 resubmission (GB300 container infra failure twice; R12 never ran).
// R12: edge compaction (thread-per-edge scan -> surviving-edge list) + warp-per-surviving-edge scatter.

#define N_USERS 100000
#define NTOT    150000
#define DIM     128
#define KP      8
#define EG      1500000
#define NLOC    65536
#define ELOC    262144
#define BB      1024
#define MAXNEED (NLOC + 2*BB)

#define OFF_PRED 0
#define OFF_GU   (BB)
#define OFF_HSUB (BB + BB*DIM)
#define OFF_PU   (BB + 2*BB*DIM)
#define OFF_PV   (BB + 2*BB*DIM + BB*KP)

__device__ float g_S[NTOT*DIM];
__device__ float g_cnt[NTOT];
__device__ int   g_mask[NTOT];
__device__ int   g_list[MAXNEED];
__device__ int   g_ncount;
__device__ int2  g_elist[EG];
__device__ int   g_ecount;
__device__ float g_GR[NTOT*DIM];
__device__ float g_XW[NLOC*DIM];
__device__ float g_LO[NLOC*DIM];
__device__ int   g_deg[NLOC];
__device__ float g_dinv[NLOC];
__device__ float g_M1[DIM*DIM];
__device__ float g_DP2[4*DIM];
__device__ float g_hsum[BB*DIM];
__device__ float g_cntB[BB];
__device__ float g_gi[BB*DIM];
__device__ float g_ru[BB*DIM];
__device__ float g_rv[BB*DIM];

#define GSMEM2 ((8192 + 8192)*4 + 512)

#define SST 132
#define WST 72
#define SSH_FLOATS (64*SST)
#define WSH_FLOATS (128*WST)
#define GSMEM3 ((SSH_FLOATS + WSH_FLOATS)*4 + 512)

__device__ __forceinline__ void atomic_add4(float* p, float a, float b, float c, float d) {
#if defined(__CUDA_ARCH__) && (__CUDA_ARCH__ >= 900)
    atomicAdd((float4*)p, make_float4(a, b, c, d));
#else
    atomicAdd(p+0, a); atomicAdd(p+1, b); atomicAdd(p+2, c); atomicAdd(p+3, d);
#endif
}

__device__ __forceinline__ float to_tf32(float x) {
    uint32_t u;
    asm("cvt.rna.tf32.f32 %0, %1;" : "=r"(u) : "f"(x));
    return __uint_as_float(u);
}

__device__ __forceinline__ void mma_tf32(float* c, uint32_t a0, uint32_t a1,
                                         uint32_t a2, uint32_t a3,
                                         uint32_t b0, uint32_t b1) {
    asm volatile("mma.sync.aligned.m16n8k8.row.col.f32.tf32.tf32.f32 "
        "{%0,%1,%2,%3}, {%4,%5,%6,%7}, {%8,%9}, {%0,%1,%2,%3};\n"
        : "+f"(c[0]), "+f"(c[1]), "+f"(c[2]), "+f"(c[3])
        : "r"(a0), "r"(a1), "r"(a2), "r"(a3), "r"(b0), "r"(b1));
}

__global__ void precompute_kernel(const float* __restrict__ lpw, const float* __restrict__ lpb,
                                  const float* __restrict__ gcw, const float* __restrict__ demb) {
    __shared__ float a[DIM]; __shared__ float d1[DIM];
    int j = threadIdx.x, bi = blockIdx.x;
    if (bi < DIM) {
        a[j] = lpw[bi*DIM + j]; __syncthreads();
        float acc = 0.f;
        for (int k = 0; k < DIM; k++) acc = fmaf(a[k], __ldg(&gcw[k*DIM + j]), acc);
        g_M1[bi*DIM + j] = acc;
    } else {
        int d = bi - DIM;
        a[j] = demb[d*DIM + j]; __syncthreads();
        float acc = lpb[j];
        for (int k = 0; k < DIM; k++) acc = fmaf(a[k], __ldg(&lpw[(DIM+k)*DIM + j]), acc);
        d1[j] = acc; __syncthreads();
        float acc2 = 0.f;
        for (int k = 0; k < DIM; k++) acc2 = fmaf(d1[k], __ldg(&gcw[k*DIM + j]), acc2);
        g_DP2[d*DIM + j] = acc2;
    }
}

__global__ void mark_kernel(const int* __restrict__ x_idx, const int* __restrict__ root_u,
                            const int* __restrict__ root_i) {
    int i = blockIdx.x*blockDim.x + threadIdx.x;
    int lane = threadIdx.x & 31;
    int n;
    if (i < NLOC)         n = x_idx[i];
    else if (i < NLOC+BB) n = root_u[i-NLOC];
    else                  n = root_i[i-NLOC-BB] + N_USERS;
    bool win = (atomicExch(&g_mask[n], 1) == 0);
    unsigned bal = __ballot_sync(0xffffffffu, win);
    int cnt = __popc(bal);
    int base = 0;
    if (lane == 0 && cnt) base = atomicAdd(&g_ncount, cnt);
    base = __shfl_sync(0xffffffffu, base, 0);
    if (win) {
        int rank = __popc(bal & ((1u << lane) - 1));
        g_list[base + rank] = n;
    }
}

__global__ void zero_S_kernel() {
    int w = (blockIdx.x*blockDim.x + threadIdx.x) >> 5;
    int lane = threadIdx.x & 31;
    if (w >= g_ncount) return;
    int n = g_list[w];
    ((float4*)(g_S + n*DIM))[lane] = make_float4(0.f, 0.f, 0.f, 0.f);
    if (lane == 0) g_cnt[n] = 0.f;
}

// Phase 1: thread-per-edge mask scan, warp-aggregated append of surviving edges.
__global__ void edge_compact_kernel(const int* __restrict__ src, const int* __restrict__ dst,
                                    const int* __restrict__ attr) {
    int i = blockIdx.x*blockDim.x + threadIdx.x;
    int lane = threadIdx.x & 31;
    int d = 0, sa = 0;
    bool keep = false;
    if (i < EG) {
        d = __ldg(&dst[i]);
        keep = (g_mask[d] != 0);
        if (keep) sa = (__ldg(&src[i]) << 1) | __ldg(&attr[i]);
    }
    unsigned bal = __ballot_sync(0xffffffffu, keep);
    int cnt = __popc(bal);
    int base = 0;
    if (lane == 0 && cnt) base = atomicAdd(&g_ecount, cnt);
    base = __shfl_sync(0xffffffffu, base, 0);
    if (keep) {
        int rank = __popc(bal & ((1u << lane) - 1));
        g_elist[base + rank] = make_int2(d, sa);
    }
}

// Phase 2: warp per surviving edge.
__global__ void edge_scatter2_kernel(const float* __restrict__ ue, const float* __restrict__ ie,
                                     const float* __restrict__ se) {
    int gw = (blockIdx.x*blockDim.x + threadIdx.x) >> 5;
    int lane = threadIdx.x & 31;
    int nw = (gridDim.x*blockDim.x) >> 5;
    float s0 = __ldg(&se[0]), s1 = __ldg(&se[1]);
    int total = g_ecount;
    for (int e = gw; e < total; e += nw) {
        int2 p = g_elist[e];
        int d = p.x;
        int sn = p.y >> 1;
        float s = (p.y & 1) ? s1 : s0;
        const float4* row = (const float4*)((sn < N_USERS) ? (ue + sn*DIM) : (ie + (sn-N_USERS)*DIM));
        float4 v = __ldg(row + lane);
        atomic_add4(g_S + d*DIM + lane*4, s*v.x, s*v.y, s*v.z, s*v.w);
        if (lane == 0) atomicAdd(&g_cnt[d], s);
    }
}

// ===================== tf32 mma GEMMs (64 rows x 64 cols per block) =====================

__device__ __forceinline__ void mma_mainloop(const float* __restrict__ SrowA,
                                             const float* __restrict__ SrowB,
                                             const float* __restrict__ Wsh,
                                             int thr, int grp, float acc[8][4]) {
    uint32_t A0[16], A1[16], A2[16], A3[16];
#pragma unroll
    for (int ks = 0; ks < 16; ks++) {
        int k0 = ks*8;
        A0[ks] = __float_as_uint(SrowA[k0 + thr]);
        A1[ks] = __float_as_uint(SrowB[k0 + thr]);
        A2[ks] = __float_as_uint(SrowA[k0 + thr + 4]);
        A3[ks] = __float_as_uint(SrowB[k0 + thr + 4]);
    }
#pragma unroll
    for (int ks = 0; ks < 16; ks++) {
        const float* Wk0 = Wsh + (ks*8 + thr)*WST + grp;
        const float* Wk1 = Wk0 + 4*WST;
#pragma unroll
        for (int j = 0; j < 8; j++) {
            uint32_t b0 = __float_as_uint(Wk0[j*8]);
            uint32_t b1 = __float_as_uint(Wk1[j*8]);
            mma_tf32(acc[j], A0[ks], A1[ks], A2[ks], A3[ks], b0, b1);
        }
    }
}

__global__ void __launch_bounds__(128, 3) gr_gemm_kernel(const float* __restrict__ ue,
        const float* __restrict__ ie, const float* __restrict__ W, const float* __restrict__ b) {
    extern __shared__ float sm[];
    float* Ssh = sm;
    float* Wsh = sm + SSH_FLOATS;
    int*   nid  = (int*)(Wsh + WSH_FLOATS);
    float* caux = (float*)(nid + 64);
    int tid = threadIdx.x;
    int total = g_ncount;
    int base = blockIdx.x * 64;
    if (base >= total) return;
    int cb = blockIdx.y * 64;

    for (int idx = tid; idx < DIM*64; idx += 128) {
        int k = idx >> 6, n = idx & 63;
        Wsh[k*WST + n] = to_tf32(__ldg(&W[k*DIM + cb + n]));
    }
    if (tid < 64) {
        int r = base + tid;
        int n = (r < total) ? g_list[r] : -1;
        nid[tid] = n; caux[tid] = (n >= 0) ? g_cnt[n] : 0.f;
    }
    __syncthreads();
    int wp = tid >> 5, lane = tid & 31;
    for (int r = wp; r < 64; r += 4) {
        int n = nid[r];
        float4 v = (n >= 0) ? ((const float4*)(g_S + n*DIM))[lane] : make_float4(0,0,0,0);
        *(float4*)(Ssh + r*SST + lane*4) =
            make_float4(to_tf32(v.x), to_tf32(v.y), to_tf32(v.z), to_tf32(v.w));
    }
    __syncthreads();

    int grp = lane >> 2, thr = lane & 3;
    const float* SrowA = Ssh + (wp*16 + grp)*SST;
    const float* SrowB = SrowA + 8*SST;
    float acc[8][4];
#pragma unroll
    for (int j = 0; j < 8; j++)
#pragma unroll
        for (int q = 0; q < 4; q++) acc[j][q] = 0.f;

    mma_mainloop(SrowA, SrowB, Wsh, thr, grp, acc);

    int rA = wp*16 + grp, rB = rA + 8;
    int nA = nid[rA], nB = nid[rB];
    float cA = caux[rA], cB = caux[rB];
#pragma unroll
    for (int j = 0; j < 8; j++) {
        int col = cb + j*8 + thr*2;
        float2 bb = __ldg((const float2*)(b + col));
        if (nA >= 0) {
            const float* emb = ((nA < N_USERS) ? ue + nA*DIM : ie + (nA-N_USERS)*DIM) + col;
            float2 e = __ldg((const float2*)emb);
            float2 o;
            o.x = e.x + fmaxf(fmaf(cA, bb.x, acc[j][0]), 0.f);
            o.y = e.y + fmaxf(fmaf(cA, bb.y, acc[j][1]), 0.f);
            *(float2*)(g_GR + nA*DIM + col) = o;
        }
        if (nB >= 0) {
            const float* emb = ((nB < N_USERS) ? ue + nB*DIM : ie + (nB-N_USERS)*DIM) + col;
            float2 e = __ldg((const float2*)emb);
            float2 o;
            o.x = e.x + fmaxf(fmaf(cB, bb.x, acc[j][2]), 0.f);
            o.y = e.y + fmaxf(fmaf(cB, bb.y, acc[j][3]), 0.f);
            *(float2*)(g_GR + nB*DIM + col) = o;
        }
    }
}

__global__ void __launch_bounds__(128, 3) xw_gemm_kernel(const int* __restrict__ x_idx,
        const int* __restrict__ dl_in) {
    extern __shared__ float sm[];
    float* Ssh = sm;
    float* Wsh = sm + SSH_FLOATS;
    int* dl = (int*)(Wsh + WSH_FLOATS);
    int tid = threadIdx.x;
    int base = blockIdx.x * 64;
    int cb = blockIdx.y * 64;

    for (int idx = tid; idx < DIM*64; idx += 128) {
        int k = idx >> 6, n = idx & 63;
        Wsh[k*WST + n] = to_tf32(g_M1[k*DIM + cb + n]);
    }
    if (tid < 64) dl[tid] = dl_in[base + tid];
    __syncthreads();
    int wp = tid >> 5, lane = tid & 31;
    for (int r = wp; r < 64; r += 4) {
        int n = __ldg(&x_idx[base + r]);
        float4 v = ((const float4*)(g_GR + n*DIM))[lane];
        *(float4*)(Ssh + r*SST + lane*4) =
            make_float4(to_tf32(v.x), to_tf32(v.y), to_tf32(v.z), to_tf32(v.w));
    }
    __syncthreads();

    int grp = lane >> 2, thr = lane & 3;
    const float* SrowA = Ssh + (wp*16 + grp)*SST;
    const float* SrowB = SrowA + 8*SST;
    float acc[8][4];
#pragma unroll
    for (int j = 0; j < 8; j++)
#pragma unroll
        for (int q = 0; q < 4; q++) acc[j][q] = 0.f;

    mma_mainloop(SrowA, SrowB, Wsh, thr, grp, acc);

    int rA = wp*16 + grp, rB = rA + 8;
    const float* dpA = g_DP2 + dl[rA]*DIM;
    const float* dpB = g_DP2 + dl[rB]*DIM;
#pragma unroll
    for (int j = 0; j < 8; j++) {
        int col = cb + j*8 + thr*2;
        float2 dA = *(const float2*)(dpA + col);
        float2 dB = *(const float2*)(dpB + col);
        *(float2*)(g_XW + (base + rA)*DIM + col) =
            make_float2(acc[j][0] + dA.x, acc[j][1] + dA.y);
        *(float2*)(g_XW + (base + rB)*DIM + col) =
            make_float2(acc[j][2] + dB.x, acc[j][3] + dB.y);
    }
}

// ===================== rest unchanged =====================

__global__ void gather_roots_kernel(const int* __restrict__ ru, const int* __restrict__ ri,
                                    float* __restrict__ out) {
    int i = blockIdx.x*blockDim.x + threadIdx.x;
    if (i >= 2*BB*32) return;
    int row = i >> 5, lane = i & 31;
    if (row < BB) {
        int n = __ldg(&ru[row]);
        ((float4*)(out + OFF_GU + row*DIM))[lane] = ((const float4*)(g_GR + n*DIM))[lane];
    } else {
        int b = row - BB;
        int n = __ldg(&ri[b]) + N_USERS;
        ((float4*)(g_gi + b*DIM))[lane] = ((const float4*)(g_GR + n*DIM))[lane];
    }
}

__global__ void __launch_bounds__(128) intent_kernel(const float* __restrict__ emb,
        const float* __restrict__ w1, const float* __restrict__ b1,
        const float* __restrict__ w2, const float* __restrict__ b2,
        const float* __restrict__ proto, float* __restrict__ out_p, float* __restrict__ out_r) {
    __shared__ float E[16][DIM]; __shared__ float T[16][DIM]; __shared__ float P[16][KP];
    int tid = threadIdx.x;
    int b0 = blockIdx.x * 16;
    for (int t = tid; t < 16*DIM; t += 128) E[t>>7][t&127] = emb[b0*DIM + t];
    __syncthreads();
    float acc[16];
#pragma unroll
    for (int r = 0; r < 16; r++) acc[r] = 0.f;
    for (int k = 0; k < DIM; k++) {
        float w = __ldg(&w1[k*DIM + tid]);
#pragma unroll
        for (int r = 0; r < 16; r++) acc[r] = fmaf(E[r][k], w, acc[r]);
    }
    float bb1 = __ldg(&b1[tid]);
#pragma unroll
    for (int r = 0; r < 16; r++) T[r][tid] = tanhf(acc[r] + bb1);
    __syncthreads();
    {
        int r = tid >> 3, c = tid & 7;
        float lg = __ldg(&b2[c]);
        for (int k = 0; k < DIM; k++) lg = fmaf(T[r][k], __ldg(&w2[k*KP + c]), lg);
        P[r][c] = lg;
    }
    __syncthreads();
    if (tid < 16) {
        float m = -1e30f;
#pragma unroll
        for (int c = 0; c < KP; c++) m = fmaxf(m, P[tid][c]);
        float e[KP], s = 0.f;
#pragma unroll
        for (int c = 0; c < KP; c++) { e[c] = expf(P[tid][c] - m); s += e[c]; }
        float inv = 1.f / s;
#pragma unroll
        for (int c = 0; c < KP; c++) {
            float p = e[c]*inv; P[tid][c] = p;
            out_p[(b0+tid)*KP + c] = p;
        }
    }
    __syncthreads();
#pragma unroll
    for (int r = 0; r < 16; r++) {
        float a = 0.f;
#pragma unroll
        for (int c = 0; c < KP; c++) a = fmaf(P[r][c], __ldg(&proto[c*DIM + tid]), a);
        out_r[(b0+r)*DIM + tid] = a;
    }
}

__global__ void deg_kernel(const int* __restrict__ ldst) {
    int i = blockIdx.x*blockDim.x + threadIdx.x;
    if (i < ELOC) atomicAdd(&g_deg[__ldg(&ldst[i])], 1);
}
__global__ void dinv_kernel() {
    int i = blockIdx.x*blockDim.x + threadIdx.x;
    if (i < NLOC) g_dinv[i] = rsqrtf((float)(g_deg[i] + 1));
}
__global__ void lo_init_kernel(const float* __restrict__ gcb) {
    int i = blockIdx.x*blockDim.x + threadIdx.x;
    if (i >= NLOC*32) return;
    int n = i >> 5, lane = i & 31;
    float di = g_dinv[n], nm = di*di;
    float4 x = ((const float4*)(g_XW + n*DIM))[lane];
    float4 b = __ldg(((const float4*)gcb) + lane);
    ((float4*)(g_LO + n*DIM))[lane] =
        make_float4(fmaf(nm,x.x,b.x), fmaf(nm,x.y,b.y), fmaf(nm,x.z,b.z), fmaf(nm,x.w,b.w));
}
__global__ void lo_scatter_kernel(const int* __restrict__ lsrc, const int* __restrict__ ldst) {
    int gw = (blockIdx.x*blockDim.x + threadIdx.x) >> 5;
    int lane = threadIdx.x & 31;
    int nw = (gridDim.x*blockDim.x) >> 5;
    for (int e = gw; e < ELOC; e += nw) {
        int s = __ldg(&lsrc[e]), d = __ldg(&ldst[e]);
        float nm = g_dinv[s] * g_dinv[d];
        float4 v = ((const float4*)(g_XW + s*DIM))[lane];
        atomic_add4(g_LO + d*DIM + lane*4, nm*v.x, nm*v.y, nm*v.z, nm*v.w);
    }
}
__global__ void pool_scatter_kernel(const int* __restrict__ batch) {
    int gw = (blockIdx.x*blockDim.x + threadIdx.x) >> 5;
    int lane = threadIdx.x & 31;
    if (gw >= NLOC) return;
    int b = __ldg(&batch[gw]);
    float4 v = ((const float4*)(g_LO + gw*DIM))[lane];
    atomic_add4(g_hsum + b*DIM + lane*4, v.x, v.y, v.z, v.w);
    if (lane == 0) atomicAdd(&g_cntB[b], 1.f);
}

__device__ __forceinline__ void gemm_core64(const float* __restrict__ Wsh,
                                            const float* __restrict__ Ssh,
                                            int r0, int tx4, float4 acc[8]) {
#pragma unroll 4
    for (int k = 0; k < DIM; k += 4) {
        float4 w0 = *(const float4*)(Wsh + (k+0)*64 + tx4);
        float4 w1 = *(const float4*)(Wsh + (k+1)*64 + tx4);
        float4 w2 = *(const float4*)(Wsh + (k+2)*64 + tx4);
        float4 w3 = *(const float4*)(Wsh + (k+3)*64 + tx4);
#pragma unroll
        for (int i = 0; i < 8; i++) {
            float4 s = *(const float4*)(Ssh + (r0+i)*DIM + k);
            acc[i].x = fmaf(s.w,w3.x, fmaf(s.z,w2.x, fmaf(s.y,w1.x, fmaf(s.x,w0.x, acc[i].x))));
            acc[i].y = fmaf(s.w,w3.y, fmaf(s.z,w2.y, fmaf(s.y,w1.y, fmaf(s.x,w0.y, acc[i].y))));
            acc[i].z = fmaf(s.w,w3.z, fmaf(s.z,w2.z, fmaf(s.y,w1.z, fmaf(s.x,w0.z, acc[i].z))));
            acc[i].w = fmaf(s.w,w3.w, fmaf(s.z,w2.w, fmaf(s.y,w1.w, fmaf(s.x,w0.w, acc[i].w))));
        }
    }
}

__device__ __forceinline__ void load_w64(float* Wsh, const float* __restrict__ W,
                                         int cb, int tid) {
    for (int t = tid; t < DIM*64/4; t += 128) {
        int k = t >> 4, c4 = (t & 15) * 4;
        *(float4*)(Wsh + k*64 + c4) = __ldg((const float4*)(W + k*DIM + cb + c4));
    }
}

__global__ void __launch_bounds__(128) pool_gemm_kernel(const float* __restrict__ pw,
        const float* __restrict__ pb, float* __restrict__ out_hsub) {
    extern __shared__ float sm[];
    float* Wsh = sm; float* Ssh = sm + 8192; float* caux = Ssh + 8192;
    int tid = threadIdx.x;
    int base = blockIdx.x * 64;
    int cb = blockIdx.y * 64;
    load_w64(Wsh, pw, cb, tid);
    if (tid < 64) caux[tid] = 1.f / fmaxf(g_cntB[base + tid], 1.f);
    __syncthreads();
    int wp = tid >> 5, lane = tid & 31;
    for (int r = wp; r < 64; r += 4) {
        float sc = caux[r];
        float4 v = ((const float4*)(g_hsum + (base + r)*DIM))[lane];
        ((float4*)(Ssh + r*DIM))[lane] = make_float4(sc*v.x, sc*v.y, sc*v.z, sc*v.w);
    }
    __syncthreads();
    int ty = tid >> 4, tx = tid & 15, r0 = ty*8, tx4 = tx*4;
    int jg = cb + tx4;
    float4 acc[8];
#pragma unroll
    for (int i = 0; i < 8; i++) acc[i] = make_float4(0.f,0.f,0.f,0.f);
    gemm_core64(Wsh, Ssh, r0, tx4, acc);
    float4 bb = __ldg((const float4*)(pb + jg));
#pragma unroll
    for (int i = 0; i < 8; i++) {
        *(float4*)(out_hsub + (base + r0 + i)*DIM + jg) =
            make_float4(tanhf(acc[i].x+bb.x), tanhf(acc[i].y+bb.y),
                        tanhf(acc[i].z+bb.z), tanhf(acc[i].w+bb.w));
    }
}

__global__ void __launch_bounds__(256) final_kernel(const float* __restrict__ w1,
        const float* __restrict__ b1, const float* __restrict__ w2,
        const float* __restrict__ b2, float* __restrict__ out) {
    __shared__ float FV[4][4*DIM]; __shared__ float H[4][64];
    int tid = threadIdx.x;
    int b0 = blockIdx.x * 4;
    for (int t = tid; t < 4*512; t += 256) {
        int r = t >> 9, k = t & 511;
        int b = b0 + r;
        float v;
        if (k < 128)      v = out[OFF_HSUB + b*DIM + k];
        else if (k < 256) v = out[OFF_GU + b*DIM + (k-128)];
        else if (k < 384) v = g_gi[b*DIM + (k-256)];
        else              v = g_ru[b*DIM + (k-384)] * g_rv[b*DIM + (k-384)];
        FV[r][k] = v;
    }
    __syncthreads();
    int r = tid >> 6, h = tid & 63;
    float acc = __ldg(&b1[h]);
    for (int k = 0; k < 512; k++) acc = fmaf(FV[r][k], __ldg(&w1[k*64 + h]), acc);
    H[r][h] = fmaxf(acc, 0.f);
    __syncthreads();
    if (tid < 4) {
        float a = __ldg(&b2[0]);
        for (int h2 = 0; h2 < 64; h2++) a = fmaf(H[tid][h2], __ldg(&w2[h2]), a);
        out[OFF_PRED + b0 + tid] = 1.f / (1.f + expf(-a));
    }
}

namespace {
struct EagerInit {
    EagerInit() {
        void* p;
        cudaGetSymbolAddress(&p, g_S);
        cudaFuncAttributes fa;
        cudaFuncGetAttributes(&fa, precompute_kernel);
        cudaFuncGetAttributes(&fa, mark_kernel);
        cudaFuncGetAttributes(&fa, zero_S_kernel);
        cudaFuncGetAttributes(&fa, edge_compact_kernel);
        cudaFuncGetAttributes(&fa, edge_scatter2_kernel);
        cudaFuncGetAttributes(&fa, gr_gemm_kernel);
        cudaFuncGetAttributes(&fa, xw_gemm_kernel);
        cudaFuncGetAttributes(&fa, gather_roots_kernel);
        cudaFuncGetAttributes(&fa, intent_kernel);
        cudaFuncGetAttributes(&fa, deg_kernel);
        cudaFuncGetAttributes(&fa, dinv_kernel);
        cudaFuncGetAttributes(&fa, lo_init_kernel);
        cudaFuncGetAttributes(&fa, lo_scatter_kernel);
        cudaFuncGetAttributes(&fa, pool_scatter_kernel);
        cudaFuncGetAttributes(&fa, pool_gemm_kernel);
        cudaFuncGetAttributes(&fa, final_kernel);
        cudaFuncSetAttribute(gr_gemm_kernel,   cudaFuncAttributeMaxDynamicSharedMemorySize, GSMEM3);
        cudaFuncSetAttribute(xw_gemm_kernel,   cudaFuncAttributeMaxDynamicSharedMemorySize, GSMEM3);
        cudaFuncSetAttribute(pool_gemm_kernel, cudaFuncAttributeMaxDynamicSharedMemorySize, GSMEM2);
    }
};
EagerInit _eager_init;
}

extern "C" void kernel_launch(void* const* d_in, const int* in_sizes, int n_in,
                              void* d_out, int out_size) {
    const int *gei = (const int*)d_in[0], *gea = (const int*)d_in[1];
    const int *root_u = (const int*)d_in[2], *root_i = (const int*)d_in[3];
    const int *x_idx = (const int*)d_in[4], *dist_label = (const int*)d_in[5];
    const int *lei = (const int*)d_in[6], *batch = (const int*)d_in[7];
    const float *ue = (const float*)d_in[8], *ie = (const float*)d_in[9];
    const float *demb = (const float*)d_in[10];
    const float *c_u = (const float*)d_in[11], *c_v = (const float*)d_in[12];
    const float *gnn_W = (const float*)d_in[13], *gnn_b = (const float*)d_in[14];
    const float *sign_emb = (const float*)d_in[15];
    const float *iw1 = (const float*)d_in[16], *ib1 = (const float*)d_in[17];
    const float *iw2 = (const float*)d_in[18], *ib2 = (const float*)d_in[19];
    const float *lpw = (const float*)d_in[20], *lpb = (const float*)d_in[21];
    const float *gcw = (const float*)d_in[22], *gcb = (const float*)d_in[23];
    const float *pw = (const float*)d_in[24], *pb = (const float*)d_in[25];
    const float *fw1 = (const float*)d_in[26], *fb1 = (const float*)d_in[27];
    const float *fw2 = (const float*)d_in[28], *fb2 = (const float*)d_in[29];
    float* out = (float*)d_out;
    const int *gsrc = gei, *gdst = gei + EG;
    const int *lsrc = lei, *ldst = lei + ELOC;

    void *pMask, *pNc, *pEc, *pDeg, *pHsum, *pCntB, *pGi, *pRu, *pRv;
    cudaGetSymbolAddress(&pMask, g_mask);
    cudaGetSymbolAddress(&pNc, g_ncount);
    cudaGetSymbolAddress(&pEc, g_ecount);
    cudaGetSymbolAddress(&pDeg, g_deg);
    cudaGetSymbolAddress(&pHsum, g_hsum);
    cudaGetSymbolAddress(&pCntB, g_cntB);
    cudaGetSymbolAddress(&pGi, g_gi);
    cudaGetSymbolAddress(&pRu, g_ru);
    cudaGetSymbolAddress(&pRv, g_rv);

    cudaMemsetAsync(pMask, 0, NTOT*4);
    cudaMemsetAsync(pNc, 0, 4);
    cudaMemsetAsync(pEc, 0, 4);
    cudaMemsetAsync(pDeg, 0, NLOC*4);
    cudaMemsetAsync(pHsum, 0, BB*DIM*4);
    cudaMemsetAsync(pCntB, 0, BB*4);

    precompute_kernel<<<DIM+4, 128>>>(lpw, lpb, gcw, demb);
    mark_kernel<<<MAXNEED/256, 256>>>(x_idx, root_u, root_i);
    zero_S_kernel<<<MAXNEED*32/256, 256>>>();
    edge_compact_kernel<<<(EG+255)/256, 256>>>(gsrc, gdst, gea);
    edge_scatter2_kernel<<<2048, 256>>>(ue, ie, sign_emb);
    gr_gemm_kernel<<<dim3(MAXNEED/64, 2), 128, GSMEM3>>>(ue, ie, gnn_W, gnn_b);
    gather_roots_kernel<<<(2*BB*32+255)/256, 256>>>(root_u, root_i, out);
    intent_kernel<<<BB/16, 128>>>(out + OFF_GU, iw1, ib1, iw2, ib2, c_u,
                                  out + OFF_PU, (float*)pRu);
    intent_kernel<<<BB/16, 128>>>((const float*)pGi, iw1, ib1, iw2, ib2, c_v,
                                  out + OFF_PV, (float*)pRv);
    xw_gemm_kernel<<<dim3(NLOC/64, 2), 128, GSMEM3>>>(x_idx, dist_label);
    deg_kernel<<<(ELOC+255)/256, 256>>>(ldst);
    dinv_kernel<<<(NLOC+255)/256, 256>>>();
    lo_init_kernel<<<(NLOC*32+255)/256, 256>>>(gcb);
    lo_scatter_kernel<<<2048, 256>>>(lsrc, ldst);
    pool_scatter_kernel<<<NLOC*32/256, 256>>>(batch);
    pool_gemm_kernel<<<dim3(BB/64, 2), 128, GSMEM2>>>(pw, pb, out + OFF_HSUB);
    final_kernel<<<BB/4, 256>>>(fw1, fb1, fw2, fb2, out);
}

// round 15
// speedup vs baseline: 1.0598x; 1.0598x over previous
#include <cuda_runtime.h>
#include <cstdint>

// R14: edge_compact v2 — 4 edges/thread (4x MLP on mask gather) + one block-level counter atomic.

#define N_USERS 100000
#define NTOT    150000
#define DIM     128
#define KP      8
#define EG      1500000
#define NLOC    65536
#define ELOC    262144
#define BB      1024
#define MAXNEED (NLOC + 2*BB)

#define OFF_PRED 0
#define OFF_GU   (BB)
#define OFF_HSUB (BB + BB*DIM)
#define OFF_PU   (BB + 2*BB*DIM)
#define OFF_PV   (BB + 2*BB*DIM + BB*KP)

__device__ float g_S[NTOT*DIM];
__device__ float g_cnt[NTOT];
__device__ int   g_mask[NTOT];
__device__ int   g_list[MAXNEED];
__device__ int   g_ncount;
__device__ int2  g_elist[EG];
__device__ int   g_ecount;
__device__ float g_GR[NTOT*DIM];
__device__ float g_XW[NLOC*DIM];
__device__ float g_LO[NLOC*DIM];
__device__ int   g_deg[NLOC];
__device__ float g_dinv[NLOC];
__device__ float g_M1[DIM*DIM];
__device__ float g_DP2[4*DIM];
__device__ float g_hsum[BB*DIM];
__device__ float g_cntB[BB];
__device__ float g_gi[BB*DIM];
__device__ float g_ru[BB*DIM];
__device__ float g_rv[BB*DIM];

#define GSMEM2 ((8192 + 8192)*4 + 512)

#define SST 132
#define WST 72
#define SSH_FLOATS (64*SST)
#define WSH_FLOATS (128*WST)
#define GSMEM3 ((SSH_FLOATS + WSH_FLOATS)*4 + 512)

__device__ __forceinline__ void atomic_add4(float* p, float a, float b, float c, float d) {
#if defined(__CUDA_ARCH__) && (__CUDA_ARCH__ >= 900)
    atomicAdd((float4*)p, make_float4(a, b, c, d));
#else
    atomicAdd(p+0, a); atomicAdd(p+1, b); atomicAdd(p+2, c); atomicAdd(p+3, d);
#endif
}

__device__ __forceinline__ float to_tf32(float x) {
    uint32_t u;
    asm("cvt.rna.tf32.f32 %0, %1;" : "=r"(u) : "f"(x));
    return __uint_as_float(u);
}

__device__ __forceinline__ void mma_tf32(float* c, uint32_t a0, uint32_t a1,
                                         uint32_t a2, uint32_t a3,
                                         uint32_t b0, uint32_t b1) {
    asm volatile("mma.sync.aligned.m16n8k8.row.col.f32.tf32.tf32.f32 "
        "{%0,%1,%2,%3}, {%4,%5,%6,%7}, {%8,%9}, {%0,%1,%2,%3};\n"
        : "+f"(c[0]), "+f"(c[1]), "+f"(c[2]), "+f"(c[3])
        : "r"(a0), "r"(a1), "r"(a2), "r"(a3), "r"(b0), "r"(b1));
}

__global__ void precompute_kernel(const float* __restrict__ lpw, const float* __restrict__ lpb,
                                  const float* __restrict__ gcw, const float* __restrict__ demb) {
    __shared__ float a[DIM]; __shared__ float d1[DIM];
    int j = threadIdx.x, bi = blockIdx.x;
    if (bi < DIM) {
        a[j] = lpw[bi*DIM + j]; __syncthreads();
        float acc = 0.f;
        for (int k = 0; k < DIM; k++) acc = fmaf(a[k], __ldg(&gcw[k*DIM + j]), acc);
        g_M1[bi*DIM + j] = acc;
    } else {
        int d = bi - DIM;
        a[j] = demb[d*DIM + j]; __syncthreads();
        float acc = lpb[j];
        for (int k = 0; k < DIM; k++) acc = fmaf(a[k], __ldg(&lpw[(DIM+k)*DIM + j]), acc);
        d1[j] = acc; __syncthreads();
        float acc2 = 0.f;
        for (int k = 0; k < DIM; k++) acc2 = fmaf(d1[k], __ldg(&gcw[k*DIM + j]), acc2);
        g_DP2[d*DIM + j] = acc2;
    }
}

__global__ void mark_kernel(const int* __restrict__ x_idx, const int* __restrict__ root_u,
                            const int* __restrict__ root_i) {
    int i = blockIdx.x*blockDim.x + threadIdx.x;
    int lane = threadIdx.x & 31;
    int n;
    if (i < NLOC)         n = x_idx[i];
    else if (i < NLOC+BB) n = root_u[i-NLOC];
    else                  n = root_i[i-NLOC-BB] + N_USERS;
    bool win = (atomicExch(&g_mask[n], 1) == 0);
    unsigned bal = __ballot_sync(0xffffffffu, win);
    int cnt = __popc(bal);
    int base = 0;
    if (lane == 0 && cnt) base = atomicAdd(&g_ncount, cnt);
    base = __shfl_sync(0xffffffffu, base, 0);
    if (win) {
        int rank = __popc(bal & ((1u << lane) - 1));
        g_list[base + rank] = n;
    }
}

__global__ void zero_S_kernel() {
    int w = (blockIdx.x*blockDim.x + threadIdx.x) >> 5;
    int lane = threadIdx.x & 31;
    if (w >= g_ncount) return;
    int n = g_list[w];
    ((float4*)(g_S + n*DIM))[lane] = make_float4(0.f, 0.f, 0.f, 0.f);
    if (lane == 0) g_cnt[n] = 0.f;
}

// Phase 1 v2: 4 edges per thread (independent chains), block-aggregated counter atomic.
#define ECPT 4
__global__ void __launch_bounds__(256) edge_compact_kernel(const int* __restrict__ src,
        const int* __restrict__ dst, const int* __restrict__ attr) {
    __shared__ int warp_off[8];
    __shared__ int block_base;
    int tid = threadIdx.x;
    int lane = tid & 31, wid = tid >> 5;
    int ebase = blockIdx.x * (256*ECPT);
    int d[ECPT], sa[ECPT];
    bool k[ECPT];
#pragma unroll
    for (int q = 0; q < ECPT; q++) {
        int e = ebase + q*256 + tid;
        k[q] = false; d[q] = 0; sa[q] = 0;
        if (e < EG) {
            d[q] = __ldg(&dst[e]);
            k[q] = (g_mask[d[q]] != 0);
        }
    }
#pragma unroll
    for (int q = 0; q < ECPT; q++) {
        if (k[q]) {
            int e = ebase + q*256 + tid;
            sa[q] = (__ldg(&src[e]) << 1) | __ldg(&attr[e]);
        }
    }
    unsigned lt = (1u << lane) - 1u;
    int pos[ECPT];
    int running = 0;
#pragma unroll
    for (int q = 0; q < ECPT; q++) {
        unsigned bal = __ballot_sync(0xffffffffu, k[q]);
        pos[q] = running + __popc(bal & lt);
        running += __popc(bal);
    }
    if (lane == 0) warp_off[wid] = running;
    __syncthreads();
    if (tid == 0) {
        int s = 0;
#pragma unroll
        for (int w = 0; w < 8; w++) { int c = warp_off[w]; warp_off[w] = s; s += c; }
        block_base = atomicAdd(&g_ecount, s);
    }
    __syncthreads();
    int base = block_base + warp_off[wid];
#pragma unroll
    for (int q = 0; q < ECPT; q++) {
        if (k[q]) g_elist[base + pos[q]] = make_int2(d[q], sa[q]);
    }
}

// Phase 2: warp per surviving edge.
__global__ void edge_scatter2_kernel(const float* __restrict__ ue, const float* __restrict__ ie,
                                     const float* __restrict__ se) {
    int gw = (blockIdx.x*blockDim.x + threadIdx.x) >> 5;
    int lane = threadIdx.x & 31;
    int nw = (gridDim.x*blockDim.x) >> 5;
    float s0 = __ldg(&se[0]), s1 = __ldg(&se[1]);
    int total = g_ecount;
    for (int e = gw; e < total; e += nw) {
        int2 p = g_elist[e];
        int d = p.x;
        int sn = p.y >> 1;
        float s = (p.y & 1) ? s1 : s0;
        const float4* row = (const float4*)((sn < N_USERS) ? (ue + sn*DIM) : (ie + (sn-N_USERS)*DIM));
        float4 v = __ldg(row + lane);
        atomic_add4(g_S + d*DIM + lane*4, s*v.x, s*v.y, s*v.z, s*v.w);
        if (lane == 0) atomicAdd(&g_cnt[d], s);
    }
}

// ===================== tf32 mma GEMMs (64 rows x 64 cols per block) =====================

__device__ __forceinline__ void mma_mainloop(const float* __restrict__ SrowA,
                                             const float* __restrict__ SrowB,
                                             const float* __restrict__ Wsh,
                                             int thr, int grp, float acc[8][4]) {
    uint32_t A0[16], A1[16], A2[16], A3[16];
#pragma unroll
    for (int ks = 0; ks < 16; ks++) {
        int k0 = ks*8;
        A0[ks] = __float_as_uint(SrowA[k0 + thr]);
        A1[ks] = __float_as_uint(SrowB[k0 + thr]);
        A2[ks] = __float_as_uint(SrowA[k0 + thr + 4]);
        A3[ks] = __float_as_uint(SrowB[k0 + thr + 4]);
    }
#pragma unroll
    for (int ks = 0; ks < 16; ks++) {
        const float* Wk0 = Wsh + (ks*8 + thr)*WST + grp;
        const float* Wk1 = Wk0 + 4*WST;
#pragma unroll
        for (int j = 0; j < 8; j++) {
            uint32_t b0 = __float_as_uint(Wk0[j*8]);
            uint32_t b1 = __float_as_uint(Wk1[j*8]);
            mma_tf32(acc[j], A0[ks], A1[ks], A2[ks], A3[ks], b0, b1);
        }
    }
}

__global__ void __launch_bounds__(128, 3) gr_gemm_kernel(const float* __restrict__ ue,
        const float* __restrict__ ie, const float* __restrict__ W, const float* __restrict__ b) {
    extern __shared__ float sm[];
    float* Ssh = sm;
    float* Wsh = sm + SSH_FLOATS;
    int*   nid  = (int*)(Wsh + WSH_FLOATS);
    float* caux = (float*)(nid + 64);
    int tid = threadIdx.x;
    int total = g_ncount;
    int base = blockIdx.x * 64;
    if (base >= total) return;
    int cb = blockIdx.y * 64;

    for (int idx = tid; idx < DIM*64; idx += 128) {
        int k = idx >> 6, n = idx & 63;
        Wsh[k*WST + n] = to_tf32(__ldg(&W[k*DIM + cb + n]));
    }
    if (tid < 64) {
        int r = base + tid;
        int n = (r < total) ? g_list[r] : -1;
        nid[tid] = n; caux[tid] = (n >= 0) ? g_cnt[n] : 0.f;
    }
    __syncthreads();
    int wp = tid >> 5, lane = tid & 31;
    for (int r = wp; r < 64; r += 4) {
        int n = nid[r];
        float4 v = (n >= 0) ? ((const float4*)(g_S + n*DIM))[lane] : make_float4(0,0,0,0);
        *(float4*)(Ssh + r*SST + lane*4) =
            make_float4(to_tf32(v.x), to_tf32(v.y), to_tf32(v.z), to_tf32(v.w));
    }
    __syncthreads();

    int grp = lane >> 2, thr = lane & 3;
    const float* SrowA = Ssh + (wp*16 + grp)*SST;
    const float* SrowB = SrowA + 8*SST;
    float acc[8][4];
#pragma unroll
    for (int j = 0; j < 8; j++)
#pragma unroll
        for (int q = 0; q < 4; q++) acc[j][q] = 0.f;

    mma_mainloop(SrowA, SrowB, Wsh, thr, grp, acc);

    int rA = wp*16 + grp, rB = rA + 8;
    int nA = nid[rA], nB = nid[rB];
    float cA = caux[rA], cB = caux[rB];
#pragma unroll
    for (int j = 0; j < 8; j++) {
        int col = cb + j*8 + thr*2;
        float2 bb = __ldg((const float2*)(b + col));
        if (nA >= 0) {
            const float* emb = ((nA < N_USERS) ? ue + nA*DIM : ie + (nA-N_USERS)*DIM) + col;
            float2 e = __ldg((const float2*)emb);
            float2 o;
            o.x = e.x + fmaxf(fmaf(cA, bb.x, acc[j][0]), 0.f);
            o.y = e.y + fmaxf(fmaf(cA, bb.y, acc[j][1]), 0.f);
            *(float2*)(g_GR + nA*DIM + col) = o;
        }
        if (nB >= 0) {
            const float* emb = ((nB < N_USERS) ? ue + nB*DIM : ie + (nB-N_USERS)*DIM) + col;
            float2 e = __ldg((const float2*)emb);
            float2 o;
            o.x = e.x + fmaxf(fmaf(cB, bb.x, acc[j][2]), 0.f);
            o.y = e.y + fmaxf(fmaf(cB, bb.y, acc[j][3]), 0.f);
            *(float2*)(g_GR + nB*DIM + col) = o;
        }
    }
}

__global__ void __launch_bounds__(128, 3) xw_gemm_kernel(const int* __restrict__ x_idx,
        const int* __restrict__ dl_in) {
    extern __shared__ float sm[];
    float* Ssh = sm;
    float* Wsh = sm + SSH_FLOATS;
    int* dl = (int*)(Wsh + WSH_FLOATS);
    int tid = threadIdx.x;
    int base = blockIdx.x * 64;
    int cb = blockIdx.y * 64;

    for (int idx = tid; idx < DIM*64; idx += 128) {
        int k = idx >> 6, n = idx & 63;
        Wsh[k*WST + n] = to_tf32(g_M1[k*DIM + cb + n]);
    }
    if (tid < 64) dl[tid] = dl_in[base + tid];
    __syncthreads();
    int wp = tid >> 5, lane = tid & 31;
    for (int r = wp; r < 64; r += 4) {
        int n = __ldg(&x_idx[base + r]);
        float4 v = ((const float4*)(g_GR + n*DIM))[lane];
        *(float4*)(Ssh + r*SST + lane*4) =
            make_float4(to_tf32(v.x), to_tf32(v.y), to_tf32(v.z), to_tf32(v.w));
    }
    __syncthreads();

    int grp = lane >> 2, thr = lane & 3;
    const float* SrowA = Ssh + (wp*16 + grp)*SST;
    const float* SrowB = SrowA + 8*SST;
    float acc[8][4];
#pragma unroll
    for (int j = 0; j < 8; j++)
#pragma unroll
        for (int q = 0; q < 4; q++) acc[j][q] = 0.f;

    mma_mainloop(SrowA, SrowB, Wsh, thr, grp, acc);

    int rA = wp*16 + grp, rB = rA + 8;
    const float* dpA = g_DP2 + dl[rA]*DIM;
    const float* dpB = g_DP2 + dl[rB]*DIM;
#pragma unroll
    for (int j = 0; j < 8; j++) {
        int col = cb + j*8 + thr*2;
        float2 dA = *(const float2*)(dpA + col);
        float2 dB = *(const float2*)(dpB + col);
        *(float2*)(g_XW + (base + rA)*DIM + col) =
            make_float2(acc[j][0] + dA.x, acc[j][1] + dA.y);
        *(float2*)(g_XW + (base + rB)*DIM + col) =
            make_float2(acc[j][2] + dB.x, acc[j][3] + dB.y);
    }
}

// ===================== rest unchanged =====================

__global__ void gather_roots_kernel(const int* __restrict__ ru, const int* __restrict__ ri,
                                    float* __restrict__ out) {
    int i = blockIdx.x*blockDim.x + threadIdx.x;
    if (i >= 2*BB*32) return;
    int row = i >> 5, lane = i & 31;
    if (row < BB) {
        int n = __ldg(&ru[row]);
        ((float4*)(out + OFF_GU + row*DIM))[lane] = ((const float4*)(g_GR + n*DIM))[lane];
    } else {
        int b = row - BB;
        int n = __ldg(&ri[b]) + N_USERS;
        ((float4*)(g_gi + b*DIM))[lane] = ((const float4*)(g_GR + n*DIM))[lane];
    }
}

__global__ void __launch_bounds__(128) intent_kernel(const float* __restrict__ emb,
        const float* __restrict__ w1, const float* __restrict__ b1,
        const float* __restrict__ w2, const float* __restrict__ b2,
        const float* __restrict__ proto, float* __restrict__ out_p, float* __restrict__ out_r) {
    __shared__ float E[16][DIM]; __shared__ float T[16][DIM]; __shared__ float P[16][KP];
    int tid = threadIdx.x;
    int b0 = blockIdx.x * 16;
    for (int t = tid; t < 16*DIM; t += 128) E[t>>7][t&127] = emb[b0*DIM + t];
    __syncthreads();
    float acc[16];
#pragma unroll
    for (int r = 0; r < 16; r++) acc[r] = 0.f;
    for (int k = 0; k < DIM; k++) {
        float w = __ldg(&w1[k*DIM + tid]);
#pragma unroll
        for (int r = 0; r < 16; r++) acc[r] = fmaf(E[r][k], w, acc[r]);
    }
    float bb1 = __ldg(&b1[tid]);
#pragma unroll
    for (int r = 0; r < 16; r++) T[r][tid] = tanhf(acc[r] + bb1);
    __syncthreads();
    {
        int r = tid >> 3, c = tid & 7;
        float lg = __ldg(&b2[c]);
        for (int k = 0; k < DIM; k++) lg = fmaf(T[r][k], __ldg(&w2[k*KP + c]), lg);
        P[r][c] = lg;
    }
    __syncthreads();
    if (tid < 16) {
        float m = -1e30f;
#pragma unroll
        for (int c = 0; c < KP; c++) m = fmaxf(m, P[tid][c]);
        float e[KP], s = 0.f;
#pragma unroll
        for (int c = 0; c < KP; c++) { e[c] = expf(P[tid][c] - m); s += e[c]; }
        float inv = 1.f / s;
#pragma unroll
        for (int c = 0; c < KP; c++) {
            float p = e[c]*inv; P[tid][c] = p;
            out_p[(b0+tid)*KP + c] = p;
        }
    }
    __syncthreads();
#pragma unroll
    for (int r = 0; r < 16; r++) {
        float a = 0.f;
#pragma unroll
        for (int c = 0; c < KP; c++) a = fmaf(P[r][c], __ldg(&proto[c*DIM + tid]), a);
        out_r[(b0+r)*DIM + tid] = a;
    }
}

__global__ void deg_kernel(const int* __restrict__ ldst) {
    int i = blockIdx.x*blockDim.x + threadIdx.x;
    if (i < ELOC) atomicAdd(&g_deg[__ldg(&ldst[i])], 1);
}
__global__ void dinv_kernel() {
    int i = blockIdx.x*blockDim.x + threadIdx.x;
    if (i < NLOC) g_dinv[i] = rsqrtf((float)(g_deg[i] + 1));
}
__global__ void lo_init_kernel(const float* __restrict__ gcb) {
    int i = blockIdx.x*blockDim.x + threadIdx.x;
    if (i >= NLOC*32) return;
    int n = i >> 5, lane = i & 31;
    float di = g_dinv[n], nm = di*di;
    float4 x = ((const float4*)(g_XW + n*DIM))[lane];
    float4 b = __ldg(((const float4*)gcb) + lane);
    ((float4*)(g_LO + n*DIM))[lane] =
        make_float4(fmaf(nm,x.x,b.x), fmaf(nm,x.y,b.y), fmaf(nm,x.z,b.z), fmaf(nm,x.w,b.w));
}
__global__ void lo_scatter_kernel(const int* __restrict__ lsrc, const int* __restrict__ ldst) {
    int gw = (blockIdx.x*blockDim.x + threadIdx.x) >> 5;
    int lane = threadIdx.x & 31;
    int nw = (gridDim.x*blockDim.x) >> 5;
    for (int e = gw; e < ELOC; e += nw) {
        int s = __ldg(&lsrc[e]), d = __ldg(&ldst[e]);
        float nm = g_dinv[s] * g_dinv[d];
        float4 v = ((const float4*)(g_XW + s*DIM))[lane];
        atomic_add4(g_LO + d*DIM + lane*4, nm*v.x, nm*v.y, nm*v.z, nm*v.w);
    }
}
__global__ void pool_scatter_kernel(const int* __restrict__ batch) {
    int gw = (blockIdx.x*blockDim.x + threadIdx.x) >> 5;
    int lane = threadIdx.x & 31;
    if (gw >= NLOC) return;
    int b = __ldg(&batch[gw]);
    float4 v = ((const float4*)(g_LO + gw*DIM))[lane];
    atomic_add4(g_hsum + b*DIM + lane*4, v.x, v.y, v.z, v.w);
    if (lane == 0) atomicAdd(&g_cntB[b], 1.f);
}

__device__ __forceinline__ void gemm_core64(const float* __restrict__ Wsh,
                                            const float* __restrict__ Ssh,
                                            int r0, int tx4, float4 acc[8]) {
#pragma unroll 4
    for (int k = 0; k < DIM; k += 4) {
        float4 w0 = *(const float4*)(Wsh + (k+0)*64 + tx4);
        float4 w1 = *(const float4*)(Wsh + (k+1)*64 + tx4);
        float4 w2 = *(const float4*)(Wsh + (k+2)*64 + tx4);
        float4 w3 = *(const float4*)(Wsh + (k+3)*64 + tx4);
#pragma unroll
        for (int i = 0; i < 8; i++) {
            float4 s = *(const float4*)(Ssh + (r0+i)*DIM + k);
            acc[i].x = fmaf(s.w,w3.x, fmaf(s.z,w2.x, fmaf(s.y,w1.x, fmaf(s.x,w0.x, acc[i].x))));
            acc[i].y = fmaf(s.w,w3.y, fmaf(s.z,w2.y, fmaf(s.y,w1.y, fmaf(s.x,w0.y, acc[i].y))));
            acc[i].z = fmaf(s.w,w3.z, fmaf(s.z,w2.z, fmaf(s.y,w1.z, fmaf(s.x,w0.z, acc[i].z))));
            acc[i].w = fmaf(s.w,w3.w, fmaf(s.z,w2.w, fmaf(s.y,w1.w, fmaf(s.x,w0.w, acc[i].w))));
        }
    }
}

__device__ __forceinline__ void load_w64(float* Wsh, const float* __restrict__ W,
                                         int cb, int tid) {
    for (int t = tid; t < DIM*64/4; t += 128) {
        int k = t >> 4, c4 = (t & 15) * 4;
        *(float4*)(Wsh + k*64 + c4) = __ldg((const float4*)(W + k*DIM + cb + c4));
    }
}

__global__ void __launch_bounds__(128) pool_gemm_kernel(const float* __restrict__ pw,
        const float* __restrict__ pb, float* __restrict__ out_hsub) {
    extern __shared__ float sm[];
    float* Wsh = sm; float* Ssh = sm + 8192; float* caux = Ssh + 8192;
    int tid = threadIdx.x;
    int base = blockIdx.x * 64;
    int cb = blockIdx.y * 64;
    load_w64(Wsh, pw, cb, tid);
    if (tid < 64) caux[tid] = 1.f / fmaxf(g_cntB[base + tid], 1.f);
    __syncthreads();
    int wp = tid >> 5, lane = tid & 31;
    for (int r = wp; r < 64; r += 4) {
        float sc = caux[r];
        float4 v = ((const float4*)(g_hsum + (base + r)*DIM))[lane];
        ((float4*)(Ssh + r*DIM))[lane] = make_float4(sc*v.x, sc*v.y, sc*v.z, sc*v.w);
    }
    __syncthreads();
    int ty = tid >> 4, tx = tid & 15, r0 = ty*8, tx4 = tx*4;
    int jg = cb + tx4;
    float4 acc[8];
#pragma unroll
    for (int i = 0; i < 8; i++) acc[i] = make_float4(0.f,0.f,0.f,0.f);
    gemm_core64(Wsh, Ssh, r0, tx4, acc);
    float4 bb = __ldg((const float4*)(pb + jg));
#pragma unroll
    for (int i = 0; i < 8; i++) {
        *(float4*)(out_hsub + (base + r0 + i)*DIM + jg) =
            make_float4(tanhf(acc[i].x+bb.x), tanhf(acc[i].y+bb.y),
                        tanhf(acc[i].z+bb.z), tanhf(acc[i].w+bb.w));
    }
}

__global__ void __launch_bounds__(256) final_kernel(const float* __restrict__ w1,
        const float* __restrict__ b1, const float* __restrict__ w2,
        const float* __restrict__ b2, float* __restrict__ out) {
    __shared__ float FV[4][4*DIM]; __shared__ float H[4][64];
    int tid = threadIdx.x;
    int b0 = blockIdx.x * 4;
    for (int t = tid; t < 4*512; t += 256) {
        int r = t >> 9, k = t & 511;
        int b = b0 + r;
        float v;
        if (k < 128)      v = out[OFF_HSUB + b*DIM + k];
        else if (k < 256) v = out[OFF_GU + b*DIM + (k-128)];
        else if (k < 384) v = g_gi[b*DIM + (k-256)];
        else              v = g_ru[b*DIM + (k-384)] * g_rv[b*DIM + (k-384)];
        FV[r][k] = v;
    }
    __syncthreads();
    int r = tid >> 6, h = tid & 63;
    float acc = __ldg(&b1[h]);
    for (int k = 0; k < 512; k++) acc = fmaf(FV[r][k], __ldg(&w1[k*64 + h]), acc);
    H[r][h] = fmaxf(acc, 0.f);
    __syncthreads();
    if (tid < 4) {
        float a = __ldg(&b2[0]);
        for (int h2 = 0; h2 < 64; h2++) a = fmaf(H[tid][h2], __ldg(&w2[h2]), a);
        out[OFF_PRED + b0 + tid] = 1.f / (1.f + expf(-a));
    }
}

namespace {
struct EagerInit {
    EagerInit() {
        void* p;
        cudaGetSymbolAddress(&p, g_S);
        cudaFuncAttributes fa;
        cudaFuncGetAttributes(&fa, precompute_kernel);
        cudaFuncGetAttributes(&fa, mark_kernel);
        cudaFuncGetAttributes(&fa, zero_S_kernel);
        cudaFuncGetAttributes(&fa, edge_compact_kernel);
        cudaFuncGetAttributes(&fa, edge_scatter2_kernel);
        cudaFuncGetAttributes(&fa, gr_gemm_kernel);
        cudaFuncGetAttributes(&fa, xw_gemm_kernel);
        cudaFuncGetAttributes(&fa, gather_roots_kernel);
        cudaFuncGetAttributes(&fa, intent_kernel);
        cudaFuncGetAttributes(&fa, deg_kernel);
        cudaFuncGetAttributes(&fa, dinv_kernel);
        cudaFuncGetAttributes(&fa, lo_init_kernel);
        cudaFuncGetAttributes(&fa, lo_scatter_kernel);
        cudaFuncGetAttributes(&fa, pool_scatter_kernel);
        cudaFuncGetAttributes(&fa, pool_gemm_kernel);
        cudaFuncGetAttributes(&fa, final_kernel);
        cudaFuncSetAttribute(gr_gemm_kernel,   cudaFuncAttributeMaxDynamicSharedMemorySize, GSMEM3);
        cudaFuncSetAttribute(xw_gemm_kernel,   cudaFuncAttributeMaxDynamicSharedMemorySize, GSMEM3);
        cudaFuncSetAttribute(pool_gemm_kernel, cudaFuncAttributeMaxDynamicSharedMemorySize, GSMEM2);
    }
};
EagerInit _eager_init;
}

extern "C" void kernel_launch(void* const* d_in, const int* in_sizes, int n_in,
                              void* d_out, int out_size) {
    const int *gei = (const int*)d_in[0], *gea = (const int*)d_in[1];
    const int *root_u = (const int*)d_in[2], *root_i = (const int*)d_in[3];
    const int *x_idx = (const int*)d_in[4], *dist_label = (const int*)d_in[5];
    const int *lei = (const int*)d_in[6], *batch = (const int*)d_in[7];
    const float *ue = (const float*)d_in[8], *ie = (const float*)d_in[9];
    const float *demb = (const float*)d_in[10];
    const float *c_u = (const float*)d_in[11], *c_v = (const float*)d_in[12];
    const float *gnn_W = (const float*)d_in[13], *gnn_b = (const float*)d_in[14];
    const float *sign_emb = (const float*)d_in[15];
    const float *iw1 = (const float*)d_in[16], *ib1 = (const float*)d_in[17];
    const float *iw2 = (const float*)d_in[18], *ib2 = (const float*)d_in[19];
    const float *lpw = (const float*)d_in[20], *lpb = (const float*)d_in[21];
    const float *gcw = (const float*)d_in[22], *gcb = (const float*)d_in[23];
    const float *pw = (const float*)d_in[24], *pb = (const float*)d_in[25];
    const float *fw1 = (const float*)d_in[26], *fb1 = (const float*)d_in[27];
    const float *fw2 = (const float*)d_in[28], *fb2 = (const float*)d_in[29];
    float* out = (float*)d_out;
    const int *gsrc = gei, *gdst = gei + EG;
    const int *lsrc = lei, *ldst = lei + ELOC;

    void *pMask, *pNc, *pEc, *pDeg, *pHsum, *pCntB, *pGi, *pRu, *pRv;
    cudaGetSymbolAddress(&pMask, g_mask);
    cudaGetSymbolAddress(&pNc, g_ncount);
    cudaGetSymbolAddress(&pEc, g_ecount);
    cudaGetSymbolAddress(&pDeg, g_deg);
    cudaGetSymbolAddress(&pHsum, g_hsum);
    cudaGetSymbolAddress(&pCntB, g_cntB);
    cudaGetSymbolAddress(&pGi, g_gi);
    cudaGetSymbolAddress(&pRu, g_ru);
    cudaGetSymbolAddress(&pRv, g_rv);

    cudaMemsetAsync(pMask, 0, NTOT*4);
    cudaMemsetAsync(pNc, 0, 4);
    cudaMemsetAsync(pEc, 0, 4);
    cudaMemsetAsync(pDeg, 0, NLOC*4);
    cudaMemsetAsync(pHsum, 0, BB*DIM*4);
    cudaMemsetAsync(pCntB, 0, BB*4);

    precompute_kernel<<<DIM+4, 128>>>(lpw, lpb, gcw, demb);
    mark_kernel<<<MAXNEED/256, 256>>>(x_idx, root_u, root_i);
    zero_S_kernel<<<MAXNEED*32/256, 256>>>();
    edge_compact_kernel<<<(EG + 256*ECPT - 1)/(256*ECPT), 256>>>(gsrc, gdst, gea);
    edge_scatter2_kernel<<<2048, 256>>>(ue, ie, sign_emb);
    gr_gemm_kernel<<<dim3(MAXNEED/64, 2), 128, GSMEM3>>>(ue, ie, gnn_W, gnn_b);
    gather_roots_kernel<<<(2*BB*32+255)/256, 256>>>(root_u, root_i, out);
    intent_kernel<<<BB/16, 128>>>(out + OFF_GU, iw1, ib1, iw2, ib2, c_u,
                                  out + OFF_PU, (float*)pRu);
    intent_kernel<<<BB/16, 128>>>((const float*)pGi, iw1, ib1, iw2, ib2, c_v,
                                  out + OFF_PV, (float*)pRv);
    xw_gemm_kernel<<<dim3(NLOC/64, 2), 128, GSMEM3>>>(x_idx, dist_label);
    deg_kernel<<<(ELOC+255)/256, 256>>>(ldst);
    dinv_kernel<<<(NLOC+255)/256, 256>>>();
    lo_init_kernel<<<(NLOC*32+255)/256, 256>>>(gcb);
    lo_scatter_kernel<<<2048, 256>>>(lsrc, ldst);
    pool_scatter_kernel<<<NLOC*32/256, 256>>>(batch);
    pool_gemm_kernel<<<dim3(BB/64, 2), 128, GSMEM2>>>(pw, pb, out + OFF_HSUB);
    final_kernel<<<BB/4, 256>>>(fw1, fb1, fw2, fb2, out);
}

// round 16
// speedup vs baseline: 1.0758x; 1.0151x over previous
#include <cuda_runtime.h>
#include <cstdint>

// R15: global edge scatter -> CSR (count in compact, range alloc, slot, warp-per-dst accumulate).
// Removes all float atomics + zero_S from the global message-passing path.

#define N_USERS 100000
#define NTOT    150000
#define DIM     128
#define KP      8
#define EG      1500000
#define NLOC    65536
#define ELOC    262144
#define BB      1024
#define MAXNEED (NLOC + 2*BB)

#define OFF_PRED 0
#define OFF_GU   (BB)
#define OFF_HSUB (BB + BB*DIM)
#define OFF_PU   (BB + 2*BB*DIM)
#define OFF_PV   (BB + 2*BB*DIM + BB*KP)

__device__ float g_S[NTOT*DIM];
__device__ float g_cnt[NTOT];
__device__ int   g_mask[NTOT];
__device__ int   g_list[MAXNEED];
__device__ int   g_ncount;
__device__ int2  g_elist[EG];
__device__ int   g_ecount;
__device__ int   g_sdeg[NTOT];
__device__ int   g_start[NTOT];
__device__ int   g_cur[NTOT];
__device__ int   g_csr[EG];
__device__ int   g_etotal;
__device__ float g_GR[NTOT*DIM];
__device__ float g_XW[NLOC*DIM];
__device__ float g_LO[NLOC*DIM];
__device__ int   g_deg[NLOC];
__device__ float g_dinv[NLOC];
__device__ float g_M1[DIM*DIM];
__device__ float g_DP2[4*DIM];
__device__ float g_hsum[BB*DIM];
__device__ float g_cntB[BB];
__device__ float g_gi[BB*DIM];
__device__ float g_ru[BB*DIM];
__device__ float g_rv[BB*DIM];

#define GSMEM2 ((8192 + 8192)*4 + 512)

#define SST 132
#define WST 72
#define SSH_FLOATS (64*SST)
#define WSH_FLOATS (128*WST)
#define GSMEM3 ((SSH_FLOATS + WSH_FLOATS)*4 + 512)

__device__ __forceinline__ void atomic_add4(float* p, float a, float b, float c, float d) {
#if defined(__CUDA_ARCH__) && (__CUDA_ARCH__ >= 900)
    atomicAdd((float4*)p, make_float4(a, b, c, d));
#else
    atomicAdd(p+0, a); atomicAdd(p+1, b); atomicAdd(p+2, c); atomicAdd(p+3, d);
#endif
}

__device__ __forceinline__ float to_tf32(float x) {
    uint32_t u;
    asm("cvt.rna.tf32.f32 %0, %1;" : "=r"(u) : "f"(x));
    return __uint_as_float(u);
}

__device__ __forceinline__ void mma_tf32(float* c, uint32_t a0, uint32_t a1,
                                         uint32_t a2, uint32_t a3,
                                         uint32_t b0, uint32_t b1) {
    asm volatile("mma.sync.aligned.m16n8k8.row.col.f32.tf32.tf32.f32 "
        "{%0,%1,%2,%3}, {%4,%5,%6,%7}, {%8,%9}, {%0,%1,%2,%3};\n"
        : "+f"(c[0]), "+f"(c[1]), "+f"(c[2]), "+f"(c[3])
        : "r"(a0), "r"(a1), "r"(a2), "r"(a3), "r"(b0), "r"(b1));
}

__global__ void precompute_kernel(const float* __restrict__ lpw, const float* __restrict__ lpb,
                                  const float* __restrict__ gcw, const float* __restrict__ demb) {
    __shared__ float a[DIM]; __shared__ float d1[DIM];
    int j = threadIdx.x, bi = blockIdx.x;
    if (bi < DIM) {
        a[j] = lpw[bi*DIM + j]; __syncthreads();
        float acc = 0.f;
        for (int k = 0; k < DIM; k++) acc = fmaf(a[k], __ldg(&gcw[k*DIM + j]), acc);
        g_M1[bi*DIM + j] = acc;
    } else {
        int d = bi - DIM;
        a[j] = demb[d*DIM + j]; __syncthreads();
        float acc = lpb[j];
        for (int k = 0; k < DIM; k++) acc = fmaf(a[k], __ldg(&lpw[(DIM+k)*DIM + j]), acc);
        d1[j] = acc; __syncthreads();
        float acc2 = 0.f;
        for (int k = 0; k < DIM; k++) acc2 = fmaf(d1[k], __ldg(&gcw[k*DIM + j]), acc2);
        g_DP2[d*DIM + j] = acc2;
    }
}

__global__ void mark_kernel(const int* __restrict__ x_idx, const int* __restrict__ root_u,
                            const int* __restrict__ root_i) {
    int i = blockIdx.x*blockDim.x + threadIdx.x;
    int lane = threadIdx.x & 31;
    int n;
    if (i < NLOC)         n = x_idx[i];
    else if (i < NLOC+BB) n = root_u[i-NLOC];
    else                  n = root_i[i-NLOC-BB] + N_USERS;
    bool win = (atomicExch(&g_mask[n], 1) == 0);
    unsigned bal = __ballot_sync(0xffffffffu, win);
    int cnt = __popc(bal);
    int base = 0;
    if (lane == 0 && cnt) base = atomicAdd(&g_ncount, cnt);
    base = __shfl_sync(0xffffffffu, base, 0);
    if (win) {
        int rank = __popc(bal & ((1u << lane) - 1));
        g_list[base + rank] = n;
        g_sdeg[n] = 0;
    }
}

// Phase 1: 4 edges/thread, block-aggregated counter; also counts per-dst surviving degree.
#define ECPT 4
__global__ void __launch_bounds__(256) edge_compact_kernel(const int* __restrict__ src,
        const int* __restrict__ dst, const int* __restrict__ attr) {
    __shared__ int warp_off[8];
    __shared__ int block_base;
    int tid = threadIdx.x;
    int lane = tid & 31, wid = tid >> 5;
    int ebase = blockIdx.x * (256*ECPT);
    int d[ECPT], sa[ECPT];
    bool k[ECPT];
#pragma unroll
    for (int q = 0; q < ECPT; q++) {
        int e = ebase + q*256 + tid;
        k[q] = false; d[q] = 0; sa[q] = 0;
        if (e < EG) {
            d[q] = __ldg(&dst[e]);
            k[q] = (g_mask[d[q]] != 0);
        }
    }
#pragma unroll
    for (int q = 0; q < ECPT; q++) {
        if (k[q]) {
            int e = ebase + q*256 + tid;
            sa[q] = (__ldg(&src[e]) << 1) | __ldg(&attr[e]);
            atomicAdd(&g_sdeg[d[q]], 1);
        }
    }
    unsigned lt = (1u << lane) - 1u;
    int pos[ECPT];
    int running = 0;
#pragma unroll
    for (int q = 0; q < ECPT; q++) {
        unsigned bal = __ballot_sync(0xffffffffu, k[q]);
        pos[q] = running + __popc(bal & lt);
        running += __popc(bal);
    }
    if (lane == 0) warp_off[wid] = running;
    __syncthreads();
    if (tid == 0) {
        int s = 0;
#pragma unroll
        for (int w = 0; w < 8; w++) { int c = warp_off[w]; warp_off[w] = s; s += c; }
        block_base = atomicAdd(&g_ecount, s);
    }
    __syncthreads();
    int base = block_base + warp_off[wid];
#pragma unroll
    for (int q = 0; q < ECPT; q++) {
        if (k[q]) g_elist[base + pos[q]] = make_int2(d[q], sa[q]);
    }
}

// CSR range allocation: warp-aggregated exclusive allocation off one counter.
__global__ void start_kernel() {
    int i = blockIdx.x*blockDim.x + threadIdx.x;
    int lane = threadIdx.x & 31;
    int total = g_ncount;
    int n = -1, s = 0;
    if (i < total) { n = g_list[i]; s = g_sdeg[n]; }
    // inclusive warp scan of s
    int incl = s;
#pragma unroll
    for (int o = 1; o < 32; o <<= 1) {
        int v = __shfl_up_sync(0xffffffffu, incl, o);
        if (lane >= o) incl += v;
    }
    int wsum = __shfl_sync(0xffffffffu, incl, 31);
    int base = 0;
    if (lane == 31 && wsum) base = atomicAdd(&g_etotal, wsum);
    base = __shfl_sync(0xffffffffu, base, 31);
    if (n >= 0) {
        int st = base + incl - s;   // exclusive
        g_start[n] = st;
        g_cur[n] = st;
    }
}

// Slot each compacted edge into its dst's CSR segment.
__global__ void csr_scatter_kernel() {
    int i = blockIdx.x*blockDim.x + threadIdx.x;
    if (i >= g_ecount) return;
    int2 p = g_elist[i];
    int slot = atomicAdd(&g_cur[p.x], 1);
    g_csr[slot] = p.y;
}

// Warp per dst node: accumulate its edges in registers, single row store. No atomics.
__global__ void edge_scatter3_kernel(const float* __restrict__ ue, const float* __restrict__ ie,
                                     const float* __restrict__ se) {
    int w = (blockIdx.x*blockDim.x + threadIdx.x) >> 5;
    int lane = threadIdx.x & 31;
    if (w >= g_ncount) return;
    float s0 = __ldg(&se[0]), s1 = __ldg(&se[1]);
    int n = g_list[w];
    int st = g_start[n];
    int m = g_sdeg[n];
    float4 acc = make_float4(0.f, 0.f, 0.f, 0.f);
    float c = 0.f;
    int i = 0;
    for (; i + 1 < m; i += 2) {
        int sa0 = g_csr[st + i], sa1 = g_csr[st + i + 1];
        int n0 = sa0 >> 1, n1 = sa1 >> 1;
        float sc0 = (sa0 & 1) ? s1 : s0;
        float sc1 = (sa1 & 1) ? s1 : s0;
        const float4* r0 = (const float4*)((n0 < N_USERS) ? (ue + n0*DIM) : (ie + (n0-N_USERS)*DIM));
        const float4* r1 = (const float4*)((n1 < N_USERS) ? (ue + n1*DIM) : (ie + (n1-N_USERS)*DIM));
        float4 v0 = __ldg(r0 + lane);
        float4 v1 = __ldg(r1 + lane);
        acc.x += sc0*v0.x + sc1*v1.x;
        acc.y += sc0*v0.y + sc1*v1.y;
        acc.z += sc0*v0.z + sc1*v1.z;
        acc.w += sc0*v0.w + sc1*v1.w;
        c += sc0 + sc1;
    }
    if (i < m) {
        int sa0 = g_csr[st + i];
        int n0 = sa0 >> 1;
        float sc0 = (sa0 & 1) ? s1 : s0;
        const float4* r0 = (const float4*)((n0 < N_USERS) ? (ue + n0*DIM) : (ie + (n0-N_USERS)*DIM));
        float4 v0 = __ldg(r0 + lane);
        acc.x += sc0*v0.x; acc.y += sc0*v0.y; acc.z += sc0*v0.z; acc.w += sc0*v0.w;
        c += sc0;
    }
    ((float4*)(g_S + n*DIM))[lane] = acc;
    if (lane == 0) g_cnt[n] = c;
}

// ===================== tf32 mma GEMMs (64 rows x 64 cols per block) =====================

__device__ __forceinline__ void mma_mainloop(const float* __restrict__ SrowA,
                                             const float* __restrict__ SrowB,
                                             const float* __restrict__ Wsh,
                                             int thr, int grp, float acc[8][4]) {
    uint32_t A0[16], A1[16], A2[16], A3[16];
#pragma unroll
    for (int ks = 0; ks < 16; ks++) {
        int k0 = ks*8;
        A0[ks] = __float_as_uint(SrowA[k0 + thr]);
        A1[ks] = __float_as_uint(SrowB[k0 + thr]);
        A2[ks] = __float_as_uint(SrowA[k0 + thr + 4]);
        A3[ks] = __float_as_uint(SrowB[k0 + thr + 4]);
    }
#pragma unroll
    for (int ks = 0; ks < 16; ks++) {
        const float* Wk0 = Wsh + (ks*8 + thr)*WST + grp;
        const float* Wk1 = Wk0 + 4*WST;
#pragma unroll
        for (int j = 0; j < 8; j++) {
            uint32_t b0 = __float_as_uint(Wk0[j*8]);
            uint32_t b1 = __float_as_uint(Wk1[j*8]);
            mma_tf32(acc[j], A0[ks], A1[ks], A2[ks], A3[ks], b0, b1);
        }
    }
}

__global__ void __launch_bounds__(128, 3) gr_gemm_kernel(const float* __restrict__ ue,
        const float* __restrict__ ie, const float* __restrict__ W, const float* __restrict__ b) {
    extern __shared__ float sm[];
    float* Ssh = sm;
    float* Wsh = sm + SSH_FLOATS;
    int*   nid  = (int*)(Wsh + WSH_FLOATS);
    float* caux = (float*)(nid + 64);
    int tid = threadIdx.x;
    int total = g_ncount;
    int base = blockIdx.x * 64;
    if (base >= total) return;
    int cb = blockIdx.y * 64;

    for (int idx = tid; idx < DIM*64; idx += 128) {
        int k = idx >> 6, n = idx & 63;
        Wsh[k*WST + n] = to_tf32(__ldg(&W[k*DIM + cb + n]));
    }
    if (tid < 64) {
        int r = base + tid;
        int n = (r < total) ? g_list[r] : -1;
        nid[tid] = n; caux[tid] = (n >= 0) ? g_cnt[n] : 0.f;
    }
    __syncthreads();
    int wp = tid >> 5, lane = tid & 31;
    for (int r = wp; r < 64; r += 4) {
        int n = nid[r];
        float4 v = (n >= 0) ? ((const float4*)(g_S + n*DIM))[lane] : make_float4(0,0,0,0);
        *(float4*)(Ssh + r*SST + lane*4) =
            make_float4(to_tf32(v.x), to_tf32(v.y), to_tf32(v.z), to_tf32(v.w));
    }
    __syncthreads();

    int grp = lane >> 2, thr = lane & 3;
    const float* SrowA = Ssh + (wp*16 + grp)*SST;
    const float* SrowB = SrowA + 8*SST;
    float acc[8][4];
#pragma unroll
    for (int j = 0; j < 8; j++)
#pragma unroll
        for (int q = 0; q < 4; q++) acc[j][q] = 0.f;

    mma_mainloop(SrowA, SrowB, Wsh, thr, grp, acc);

    int rA = wp*16 + grp, rB = rA + 8;
    int nA = nid[rA], nB = nid[rB];
    float cA = caux[rA], cB = caux[rB];
#pragma unroll
    for (int j = 0; j < 8; j++) {
        int col = cb + j*8 + thr*2;
        float2 bb = __ldg((const float2*)(b + col));
        if (nA >= 0) {
            const float* emb = ((nA < N_USERS) ? ue + nA*DIM : ie + (nA-N_USERS)*DIM) + col;
            float2 e = __ldg((const float2*)emb);
            float2 o;
            o.x = e.x + fmaxf(fmaf(cA, bb.x, acc[j][0]), 0.f);
            o.y = e.y + fmaxf(fmaf(cA, bb.y, acc[j][1]), 0.f);
            *(float2*)(g_GR + nA*DIM + col) = o;
        }
        if (nB >= 0) {
            const float* emb = ((nB < N_USERS) ? ue + nB*DIM : ie + (nB-N_USERS)*DIM) + col;
            float2 e = __ldg((const float2*)emb);
            float2 o;
            o.x = e.x + fmaxf(fmaf(cB, bb.x, acc[j][2]), 0.f);
            o.y = e.y + fmaxf(fmaf(cB, bb.y, acc[j][3]), 0.f);
            *(float2*)(g_GR + nB*DIM + col) = o;
        }
    }
}

__global__ void __launch_bounds__(128, 3) xw_gemm_kernel(const int* __restrict__ x_idx,
        const int* __restrict__ dl_in) {
    extern __shared__ float sm[];
    float* Ssh = sm;
    float* Wsh = sm + SSH_FLOATS;
    int* dl = (int*)(Wsh + WSH_FLOATS);
    int tid = threadIdx.x;
    int base = blockIdx.x * 64;
    int cb = blockIdx.y * 64;

    for (int idx = tid; idx < DIM*64; idx += 128) {
        int k = idx >> 6, n = idx & 63;
        Wsh[k*WST + n] = to_tf32(g_M1[k*DIM + cb + n]);
    }
    if (tid < 64) dl[tid] = dl_in[base + tid];
    __syncthreads();
    int wp = tid >> 5, lane = tid & 31;
    for (int r = wp; r < 64; r += 4) {
        int n = __ldg(&x_idx[base + r]);
        float4 v = ((const float4*)(g_GR + n*DIM))[lane];
        *(float4*)(Ssh + r*SST + lane*4) =
            make_float4(to_tf32(v.x), to_tf32(v.y), to_tf32(v.z), to_tf32(v.w));
    }
    __syncthreads();

    int grp = lane >> 2, thr = lane & 3;
    const float* SrowA = Ssh + (wp*16 + grp)*SST;
    const float* SrowB = SrowA + 8*SST;
    float acc[8][4];
#pragma unroll
    for (int j = 0; j < 8; j++)
#pragma unroll
        for (int q = 0; q < 4; q++) acc[j][q] = 0.f;

    mma_mainloop(SrowA, SrowB, Wsh, thr, grp, acc);

    int rA = wp*16 + grp, rB = rA + 8;
    const float* dpA = g_DP2 + dl[rA]*DIM;
    const float* dpB = g_DP2 + dl[rB]*DIM;
#pragma unroll
    for (int j = 0; j < 8; j++) {
        int col = cb + j*8 + thr*2;
        float2 dA = *(const float2*)(dpA + col);
        float2 dB = *(const float2*)(dpB + col);
        *(float2*)(g_XW + (base + rA)*DIM + col) =
            make_float2(acc[j][0] + dA.x, acc[j][1] + dA.y);
        *(float2*)(g_XW + (base + rB)*DIM + col) =
            make_float2(acc[j][2] + dB.x, acc[j][3] + dB.y);
    }
}

// ===================== rest unchanged =====================

__global__ void gather_roots_kernel(const int* __restrict__ ru, const int* __restrict__ ri,
                                    float* __restrict__ out) {
    int i = blockIdx.x*blockDim.x + threadIdx.x;
    if (i >= 2*BB*32) return;
    int row = i >> 5, lane = i & 31;
    if (row < BB) {
        int n = __ldg(&ru[row]);
        ((float4*)(out + OFF_GU + row*DIM))[lane] = ((const float4*)(g_GR + n*DIM))[lane];
    } else {
        int b = row - BB;
        int n = __ldg(&ri[b]) + N_USERS;
        ((float4*)(g_gi + b*DIM))[lane] = ((const float4*)(g_GR + n*DIM))[lane];
    }
}

__global__ void __launch_bounds__(128) intent_kernel(const float* __restrict__ emb,
        const float* __restrict__ w1, const float* __restrict__ b1,
        const float* __restrict__ w2, const float* __restrict__ b2,
        const float* __restrict__ proto, float* __restrict__ out_p, float* __restrict__ out_r) {
    __shared__ float E[16][DIM]; __shared__ float T[16][DIM]; __shared__ float P[16][KP];
    int tid = threadIdx.x;
    int b0 = blockIdx.x * 16;
    for (int t = tid; t < 16*DIM; t += 128) E[t>>7][t&127] = emb[b0*DIM + t];
    __syncthreads();
    float acc[16];
#pragma unroll
    for (int r = 0; r < 16; r++) acc[r] = 0.f;
    for (int k = 0; k < DIM; k++) {
        float w = __ldg(&w1[k*DIM + tid]);
#pragma unroll
        for (int r = 0; r < 16; r++) acc[r] = fmaf(E[r][k], w, acc[r]);
    }
    float bb1 = __ldg(&b1[tid]);
#pragma unroll
    for (int r = 0; r < 16; r++) T[r][tid] = tanhf(acc[r] + bb1);
    __syncthreads();
    {
        int r = tid >> 3, c = tid & 7;
        float lg = __ldg(&b2[c]);
        for (int k = 0; k < DIM; k++) lg = fmaf(T[r][k], __ldg(&w2[k*KP + c]), lg);
        P[r][c] = lg;
    }
    __syncthreads();
    if (tid < 16) {
        float m = -1e30f;
#pragma unroll
        for (int c = 0; c < KP; c++) m = fmaxf(m, P[tid][c]);
        float e[KP], s = 0.f;
#pragma unroll
        for (int c = 0; c < KP; c++) { e[c] = expf(P[tid][c] - m); s += e[c]; }
        float inv = 1.f / s;
#pragma unroll
        for (int c = 0; c < KP; c++) {
            float p = e[c]*inv; P[tid][c] = p;
            out_p[(b0+tid)*KP + c] = p;
        }
    }
    __syncthreads();
#pragma unroll
    for (int r = 0; r < 16; r++) {
        float a = 0.f;
#pragma unroll
        for (int c = 0; c < KP; c++) a = fmaf(P[r][c], __ldg(&proto[c*DIM + tid]), a);
        out_r[(b0+r)*DIM + tid] = a;
    }
}

__global__ void deg_kernel(const int* __restrict__ ldst) {
    int i = blockIdx.x*blockDim.x + threadIdx.x;
    if (i < ELOC) atomicAdd(&g_deg[__ldg(&ldst[i])], 1);
}
__global__ void dinv_kernel() {
    int i = blockIdx.x*blockDim.x + threadIdx.x;
    if (i < NLOC) g_dinv[i] = rsqrtf((float)(g_deg[i] + 1));
}
__global__ void lo_init_kernel(const float* __restrict__ gcb) {
    int i = blockIdx.x*blockDim.x + threadIdx.x;
    if (i >= NLOC*32) return;
    int n = i >> 5, lane = i & 31;
    float di = g_dinv[n], nm = di*di;
    float4 x = ((const float4*)(g_XW + n*DIM))[lane];
    float4 b = __ldg(((const float4*)gcb) + lane);
    ((float4*)(g_LO + n*DIM))[lane] =
        make_float4(fmaf(nm,x.x,b.x), fmaf(nm,x.y,b.y), fmaf(nm,x.z,b.z), fmaf(nm,x.w,b.w));
}
__global__ void lo_scatter_kernel(const int* __restrict__ lsrc, const int* __restrict__ ldst) {
    int gw = (blockIdx.x*blockDim.x + threadIdx.x) >> 5;
    int lane = threadIdx.x & 31;
    int nw = (gridDim.x*blockDim.x) >> 5;
    for (int e = gw; e < ELOC; e += nw) {
        int s = __ldg(&lsrc[e]), d = __ldg(&ldst[e]);
        float nm = g_dinv[s] * g_dinv[d];
        float4 v = ((const float4*)(g_XW + s*DIM))[lane];
        atomic_add4(g_LO + d*DIM + lane*4, nm*v.x, nm*v.y, nm*v.z, nm*v.w);
    }
}
__global__ void pool_scatter_kernel(const int* __restrict__ batch) {
    int gw = (blockIdx.x*blockDim.x + threadIdx.x) >> 5;
    int lane = threadIdx.x & 31;
    if (gw >= NLOC) return;
    int b = __ldg(&batch[gw]);
    float4 v = ((const float4*)(g_LO + gw*DIM))[lane];
    atomic_add4(g_hsum + b*DIM + lane*4, v.x, v.y, v.z, v.w);
    if (lane == 0) atomicAdd(&g_cntB[b], 1.f);
}

__device__ __forceinline__ void gemm_core64(const float* __restrict__ Wsh,
                                            const float* __restrict__ Ssh,
                                            int r0, int tx4, float4 acc[8]) {
#pragma unroll 4
    for (int k = 0; k < DIM; k += 4) {
        float4 w0 = *(const float4*)(Wsh + (k+0)*64 + tx4);
        float4 w1 = *(const float4*)(Wsh + (k+1)*64 + tx4);
        float4 w2 = *(const float4*)(Wsh + (k+2)*64 + tx4);
        float4 w3 = *(const float4*)(Wsh + (k+3)*64 + tx4);
#pragma unroll
        for (int i = 0; i < 8; i++) {
            float4 s = *(const float4*)(Ssh + (r0+i)*DIM + k);
            acc[i].x = fmaf(s.w,w3.x, fmaf(s.z,w2.x, fmaf(s.y,w1.x, fmaf(s.x,w0.x, acc[i].x))));
            acc[i].y = fmaf(s.w,w3.y, fmaf(s.z,w2.y, fmaf(s.y,w1.y, fmaf(s.x,w0.y, acc[i].y))));
            acc[i].z = fmaf(s.w,w3.z, fmaf(s.z,w2.z, fmaf(s.y,w1.z, fmaf(s.x,w0.z, acc[i].z))));
            acc[i].w = fmaf(s.w,w3.w, fmaf(s.z,w2.w, fmaf(s.y,w1.w, fmaf(s.x,w0.w, acc[i].w))));
        }
    }
}

__device__ __forceinline__ void load_w64(float* Wsh, const float* __restrict__ W,
                                         int cb, int tid) {
    for (int t = tid; t < DIM*64/4; t += 128) {
        int k = t >> 4, c4 = (t & 15) * 4;
        *(float4*)(Wsh + k*64 + c4) = __ldg((const float4*)(W + k*DIM + cb + c4));
    }
}

__global__ void __launch_bounds__(128) pool_gemm_kernel(const float* __restrict__ pw,
        const float* __restrict__ pb, float* __restrict__ out_hsub) {
    extern __shared__ float sm[];
    float* Wsh = sm; float* Ssh = sm + 8192; float* caux = Ssh + 8192;
    int tid = threadIdx.x;
    int base = blockIdx.x * 64;
    int cb = blockIdx.y * 64;
    load_w64(Wsh, pw, cb, tid);
    if (tid < 64) caux[tid] = 1.f / fmaxf(g_cntB[base + tid], 1.f);
    __syncthreads();
    int wp = tid >> 5, lane = tid & 31;
    for (int r = wp; r < 64; r += 4) {
        float sc = caux[r];
        float4 v = ((const float4*)(g_hsum + (base + r)*DIM))[lane];
        ((float4*)(Ssh + r*DIM))[lane] = make_float4(sc*v.x, sc*v.y, sc*v.z, sc*v.w);
    }
    __syncthreads();
    int ty = tid >> 4, tx = tid & 15, r0 = ty*8, tx4 = tx*4;
    int jg = cb + tx4;
    float4 acc[8];
#pragma unroll
    for (int i = 0; i < 8; i++) acc[i] = make_float4(0.f,0.f,0.f,0.f);
    gemm_core64(Wsh, Ssh, r0, tx4, acc);
    float4 bb = __ldg((const float4*)(pb + jg));
#pragma unroll
    for (int i = 0; i < 8; i++) {
        *(float4*)(out_hsub + (base + r0 + i)*DIM + jg) =
            make_float4(tanhf(acc[i].x+bb.x), tanhf(acc[i].y+bb.y),
                        tanhf(acc[i].z+bb.z), tanhf(acc[i].w+bb.w));
    }
}

__global__ void __launch_bounds__(256) final_kernel(const float* __restrict__ w1,
        const float* __restrict__ b1, const float* __restrict__ w2,
        const float* __restrict__ b2, float* __restrict__ out) {
    __shared__ float FV[4][4*DIM]; __shared__ float H[4][64];
    int tid = threadIdx.x;
    int b0 = blockIdx.x * 4;
    for (int t = tid; t < 4*512; t += 256) {
        int r = t >> 9, k = t & 511;
        int b = b0 + r;
        float v;
        if (k < 128)      v = out[OFF_HSUB + b*DIM + k];
        else if (k < 256) v = out[OFF_GU + b*DIM + (k-128)];
        else if (k < 384) v = g_gi[b*DIM + (k-256)];
        else              v = g_ru[b*DIM + (k-384)] * g_rv[b*DIM + (k-384)];
        FV[r][k] = v;
    }
    __syncthreads();
    int r = tid >> 6, h = tid & 63;
    float acc = __ldg(&b1[h]);
    for (int k = 0; k < 512; k++) acc = fmaf(FV[r][k], __ldg(&w1[k*64 + h]), acc);
    H[r][h] = fmaxf(acc, 0.f);
    __syncthreads();
    if (tid < 4) {
        float a = __ldg(&b2[0]);
        for (int h2 = 0; h2 < 64; h2++) a = fmaf(H[tid][h2], __ldg(&w2[h2]), a);
        out[OFF_PRED + b0 + tid] = 1.f / (1.f + expf(-a));
    }
}

namespace {
struct EagerInit {
    EagerInit() {
        void* p;
        cudaGetSymbolAddress(&p, g_S);
        cudaFuncAttributes fa;
        cudaFuncGetAttributes(&fa, precompute_kernel);
        cudaFuncGetAttributes(&fa, mark_kernel);
        cudaFuncGetAttributes(&fa, edge_compact_kernel);
        cudaFuncGetAttributes(&fa, start_kernel);
        cudaFuncGetAttributes(&fa, csr_scatter_kernel);
        cudaFuncGetAttributes(&fa, edge_scatter3_kernel);
        cudaFuncGetAttributes(&fa, gr_gemm_kernel);
        cudaFuncGetAttributes(&fa, xw_gemm_kernel);
        cudaFuncGetAttributes(&fa, gather_roots_kernel);
        cudaFuncGetAttributes(&fa, intent_kernel);
        cudaFuncGetAttributes(&fa, deg_kernel);
        cudaFuncGetAttributes(&fa, dinv_kernel);
        cudaFuncGetAttributes(&fa, lo_init_kernel);
        cudaFuncGetAttributes(&fa, lo_scatter_kernel);
        cudaFuncGetAttributes(&fa, pool_scatter_kernel);
        cudaFuncGetAttributes(&fa, pool_gemm_kernel);
        cudaFuncGetAttributes(&fa, final_kernel);
        cudaFuncSetAttribute(gr_gemm_kernel,   cudaFuncAttributeMaxDynamicSharedMemorySize, GSMEM3);
        cudaFuncSetAttribute(xw_gemm_kernel,   cudaFuncAttributeMaxDynamicSharedMemorySize, GSMEM3);
        cudaFuncSetAttribute(pool_gemm_kernel, cudaFuncAttributeMaxDynamicSharedMemorySize, GSMEM2);
    }
};
EagerInit _eager_init;
}

extern "C" void kernel_launch(void* const* d_in, const int* in_sizes, int n_in,
                              void* d_out, int out_size) {
    const int *gei = (const int*)d_in[0], *gea = (const int*)d_in[1];
    const int *root_u = (const int*)d_in[2], *root_i = (const int*)d_in[3];
    const int *x_idx = (const int*)d_in[4], *dist_label = (const int*)d_in[5];
    const int *lei = (const int*)d_in[6], *batch = (const int*)d_in[7];
    const float *ue = (const float*)d_in[8], *ie = (const float*)d_in[9];
    const float *demb = (const float*)d_in[10];
    const float *c_u = (const float*)d_in[11], *c_v = (const float*)d_in[12];
    const float *gnn_W = (const float*)d_in[13], *gnn_b = (const float*)d_in[14];
    const float *sign_emb = (const float*)d_in[15];
    const float *iw1 = (const float*)d_in[16], *ib1 = (const float*)d_in[17];
    const float *iw2 = (const float*)d_in[18], *ib2 = (const float*)d_in[19];
    const float *lpw = (const float*)d_in[20], *lpb = (const float*)d_in[21];
    const float *gcw = (const float*)d_in[22], *gcb = (const float*)d_in[23];
    const float *pw = (const float*)d_in[24], *pb = (const float*)d_in[25];
    const float *fw1 = (const float*)d_in[26], *fb1 = (const float*)d_in[27];
    const float *fw2 = (const float*)d_in[28], *fb2 = (const float*)d_in[29];
    float* out = (float*)d_out;
    const int *gsrc = gei, *gdst = gei + EG;
    const int *lsrc = lei, *ldst = lei + ELOC;

    void *pMask, *pNc, *pEc, *pEt, *pDeg, *pHsum, *pCntB, *pGi, *pRu, *pRv;
    cudaGetSymbolAddress(&pMask, g_mask);
    cudaGetSymbolAddress(&pNc, g_ncount);
    cudaGetSymbolAddress(&pEc, g_ecount);
    cudaGetSymbolAddress(&pEt, g_etotal);
    cudaGetSymbolAddress(&pDeg, g_deg);
    cudaGetSymbolAddress(&pHsum, g_hsum);
    cudaGetSymbolAddress(&pCntB, g_cntB);
    cudaGetSymbolAddress(&pGi, g_gi);
    cudaGetSymbolAddress(&pRu, g_ru);
    cudaGetSymbolAddress(&pRv, g_rv);

    cudaMemsetAsync(pMask, 0, NTOT*4);
    cudaMemsetAsync(pNc, 0, 4);
    cudaMemsetAsync(pEc, 0, 4);
    cudaMemsetAsync(pEt, 0, 4);
    cudaMemsetAsync(pDeg, 0, NLOC*4);
    cudaMemsetAsync(pHsum, 0, BB*DIM*4);
    cudaMemsetAsync(pCntB, 0, BB*4);

    precompute_kernel<<<DIM+4, 128>>>(lpw, lpb, gcw, demb);
    mark_kernel<<<MAXNEED/256, 256>>>(x_idx, root_u, root_i);
    edge_compact_kernel<<<(EG + 256*ECPT - 1)/(256*ECPT), 256>>>(gsrc, gdst, gea);
    start_kernel<<<(MAXNEED+255)/256, 256>>>();
    csr_scatter_kernel<<<(EG+255)/256, 256>>>();
    edge_scatter3_kernel<<<MAXNEED*32/256, 256>>>(ue, ie, sign_emb);
    gr_gemm_kernel<<<dim3(MAXNEED/64, 2), 128, GSMEM3>>>(ue, ie, gnn_W, gnn_b);
    gather_roots_kernel<<<(2*BB*32+255)/256, 256>>>(root_u, root_i, out);
    intent_kernel<<<BB/16, 128>>>(out + OFF_GU, iw1, ib1, iw2, ib2, c_u,
                                  out + OFF_PU, (float*)pRu);
    intent_kernel<<<BB/16, 128>>>((const float*)pGi, iw1, ib1, iw2, ib2, c_v,
                                  out + OFF_PV, (float*)pRv);
    xw_gemm_kernel<<<dim3(NLOC/64, 2), 128, GSMEM3>>>(x_idx, dist_label);
    deg_kernel<<<(ELOC+255)/256, 256>>>(ldst);
    dinv_kernel<<<(NLOC+255)/256, 256>>>();
    lo_init_kernel<<<(NLOC*32+255)/256, 256>>>(gcb);
    lo_scatter_kernel<<<2048, 256>>>(lsrc, ldst);
    pool_scatter_kernel<<<NLOC*32/256, 256>>>(batch);
    pool_gemm_kernel<<<dim3(BB/64, 2), 128, GSMEM2>>>(pw, pb, out + OFF_HSUB);
    final_kernel<<<BB/4, 256>>>(fw1, fb1, fw2, fb2, out);
}

// round 17
// speedup vs baseline: 1.1291x; 1.0495x over previous
#include <cuda_runtime.h>
#include <cstdint>

// R16: local GCN path -> CSR + fused warp-per-node accumulate straight into pooled hsum.
// Removes lo_init / lo_scatter / pool_scatter and the entire g_LO round-trip.

#define N_USERS 100000
#define NTOT    150000
#define DIM     128
#define KP      8
#define EG      1500000
#define NLOC    65536
#define ELOC    262144
#define BB      1024
#define MAXNEED (NLOC + 2*BB)

#define OFF_PRED 0
#define OFF_GU   (BB)
#define OFF_HSUB (BB + BB*DIM)
#define OFF_PU   (BB + 2*BB*DIM)
#define OFF_PV   (BB + 2*BB*DIM + BB*KP)

__device__ float g_S[NTOT*DIM];
__device__ float g_cnt[NTOT];
__device__ int   g_mask[NTOT];
__device__ int   g_list[MAXNEED];
__device__ int   g_ncount;
__device__ int2  g_elist[EG];
__device__ int   g_ecount;
__device__ int   g_sdeg[NTOT];
__device__ int   g_start[NTOT];
__device__ int   g_cur[NTOT];
__device__ int   g_csr[EG];
__device__ int   g_etotal;
__device__ int   g_ls[NLOC];
__device__ int   g_lc[NLOC];
__device__ int   g_lcsr[ELOC];
__device__ int   g_ltotal;
__device__ float g_GR[NTOT*DIM];
__device__ float g_XW[NLOC*DIM];
__device__ int   g_deg[NLOC];
__device__ float g_dinv[NLOC];
__device__ float g_M1[DIM*DIM];
__device__ float g_DP2[4*DIM];
__device__ float g_hsum[BB*DIM];
__device__ float g_cntB[BB];
__device__ float g_gi[BB*DIM];
__device__ float g_ru[BB*DIM];
__device__ float g_rv[BB*DIM];

#define GSMEM2 ((8192 + 8192)*4 + 512)

#define SST 132
#define WST 72
#define SSH_FLOATS (64*SST)
#define WSH_FLOATS (128*WST)
#define GSMEM3 ((SSH_FLOATS + WSH_FLOATS)*4 + 512)

__device__ __forceinline__ void atomic_add4(float* p, float a, float b, float c, float d) {
#if defined(__CUDA_ARCH__) && (__CUDA_ARCH__ >= 900)
    atomicAdd((float4*)p, make_float4(a, b, c, d));
#else
    atomicAdd(p+0, a); atomicAdd(p+1, b); atomicAdd(p+2, c); atomicAdd(p+3, d);
#endif
}

__device__ __forceinline__ float to_tf32(float x) {
    uint32_t u;
    asm("cvt.rna.tf32.f32 %0, %1;" : "=r"(u) : "f"(x));
    return __uint_as_float(u);
}

__device__ __forceinline__ void mma_tf32(float* c, uint32_t a0, uint32_t a1,
                                         uint32_t a2, uint32_t a3,
                                         uint32_t b0, uint32_t b1) {
    asm volatile("mma.sync.aligned.m16n8k8.row.col.f32.tf32.tf32.f32 "
        "{%0,%1,%2,%3}, {%4,%5,%6,%7}, {%8,%9}, {%0,%1,%2,%3};\n"
        : "+f"(c[0]), "+f"(c[1]), "+f"(c[2]), "+f"(c[3])
        : "r"(a0), "r"(a1), "r"(a2), "r"(a3), "r"(b0), "r"(b1));
}

__global__ void precompute_kernel(const float* __restrict__ lpw, const float* __restrict__ lpb,
                                  const float* __restrict__ gcw, const float* __restrict__ demb) {
    __shared__ float a[DIM]; __shared__ float d1[DIM];
    int j = threadIdx.x, bi = blockIdx.x;
    if (bi < DIM) {
        a[j] = lpw[bi*DIM + j]; __syncthreads();
        float acc = 0.f;
        for (int k = 0; k < DIM; k++) acc = fmaf(a[k], __ldg(&gcw[k*DIM + j]), acc);
        g_M1[bi*DIM + j] = acc;
    } else {
        int d = bi - DIM;
        a[j] = demb[d*DIM + j]; __syncthreads();
        float acc = lpb[j];
        for (int k = 0; k < DIM; k++) acc = fmaf(a[k], __ldg(&lpw[(DIM+k)*DIM + j]), acc);
        d1[j] = acc; __syncthreads();
        float acc2 = 0.f;
        for (int k = 0; k < DIM; k++) acc2 = fmaf(d1[k], __ldg(&gcw[k*DIM + j]), acc2);
        g_DP2[d*DIM + j] = acc2;
    }
}

__global__ void mark_kernel(const int* __restrict__ x_idx, const int* __restrict__ root_u,
                            const int* __restrict__ root_i) {
    int i = blockIdx.x*blockDim.x + threadIdx.x;
    int lane = threadIdx.x & 31;
    int n;
    if (i < NLOC)         n = x_idx[i];
    else if (i < NLOC+BB) n = root_u[i-NLOC];
    else                  n = root_i[i-NLOC-BB] + N_USERS;
    bool win = (atomicExch(&g_mask[n], 1) == 0);
    unsigned bal = __ballot_sync(0xffffffffu, win);
    int cnt = __popc(bal);
    int base = 0;
    if (lane == 0 && cnt) base = atomicAdd(&g_ncount, cnt);
    base = __shfl_sync(0xffffffffu, base, 0);
    if (win) {
        int rank = __popc(bal & ((1u << lane) - 1));
        g_list[base + rank] = n;
        g_sdeg[n] = 0;
    }
}

#define ECPT 4
__global__ void __launch_bounds__(256) edge_compact_kernel(const int* __restrict__ src,
        const int* __restrict__ dst, const int* __restrict__ attr) {
    __shared__ int warp_off[8];
    __shared__ int block_base;
    int tid = threadIdx.x;
    int lane = tid & 31, wid = tid >> 5;
    int ebase = blockIdx.x * (256*ECPT);
    int d[ECPT], sa[ECPT];
    bool k[ECPT];
#pragma unroll
    for (int q = 0; q < ECPT; q++) {
        int e = ebase + q*256 + tid;
        k[q] = false; d[q] = 0; sa[q] = 0;
        if (e < EG) {
            d[q] = __ldg(&dst[e]);
            k[q] = (g_mask[d[q]] != 0);
        }
    }
#pragma unroll
    for (int q = 0; q < ECPT; q++) {
        if (k[q]) {
            int e = ebase + q*256 + tid;
            sa[q] = (__ldg(&src[e]) << 1) | __ldg(&attr[e]);
            atomicAdd(&g_sdeg[d[q]], 1);
        }
    }
    unsigned lt = (1u << lane) - 1u;
    int pos[ECPT];
    int running = 0;
#pragma unroll
    for (int q = 0; q < ECPT; q++) {
        unsigned bal = __ballot_sync(0xffffffffu, k[q]);
        pos[q] = running + __popc(bal & lt);
        running += __popc(bal);
    }
    if (lane == 0) warp_off[wid] = running;
    __syncthreads();
    if (tid == 0) {
        int s = 0;
#pragma unroll
        for (int w = 0; w < 8; w++) { int c = warp_off[w]; warp_off[w] = s; s += c; }
        block_base = atomicAdd(&g_ecount, s);
    }
    __syncthreads();
    int base = block_base + warp_off[wid];
#pragma unroll
    for (int q = 0; q < ECPT; q++) {
        if (k[q]) g_elist[base + pos[q]] = make_int2(d[q], sa[q]);
    }
}

__global__ void start_kernel() {
    int i = blockIdx.x*blockDim.x + threadIdx.x;
    int lane = threadIdx.x & 31;
    int total = g_ncount;
    int n = -1, s = 0;
    if (i < total) { n = g_list[i]; s = g_sdeg[n]; }
    int incl = s;
#pragma unroll
    for (int o = 1; o < 32; o <<= 1) {
        int v = __shfl_up_sync(0xffffffffu, incl, o);
        if (lane >= o) incl += v;
    }
    int wsum = __shfl_sync(0xffffffffu, incl, 31);
    int base = 0;
    if (lane == 31 && wsum) base = atomicAdd(&g_etotal, wsum);
    base = __shfl_sync(0xffffffffu, base, 31);
    if (n >= 0) {
        int st = base + incl - s;
        g_start[n] = st;
        g_cur[n] = st;
    }
}

__global__ void csr_scatter_kernel() {
    int i = blockIdx.x*blockDim.x + threadIdx.x;
    if (i >= g_ecount) return;
    int2 p = g_elist[i];
    int slot = atomicAdd(&g_cur[p.x], 1);
    g_csr[slot] = p.y;
}

__global__ void edge_scatter3_kernel(const float* __restrict__ ue, const float* __restrict__ ie,
                                     const float* __restrict__ se) {
    int w = (blockIdx.x*blockDim.x + threadIdx.x) >> 5;
    int lane = threadIdx.x & 31;
    if (w >= g_ncount) return;
    float s0 = __ldg(&se[0]), s1 = __ldg(&se[1]);
    int n = g_list[w];
    int st = g_start[n];
    int m = g_sdeg[n];
    float4 acc = make_float4(0.f, 0.f, 0.f, 0.f);
    float c = 0.f;
    int i = 0;
    for (; i + 1 < m; i += 2) {
        int sa0 = g_csr[st + i], sa1 = g_csr[st + i + 1];
        int n0 = sa0 >> 1, n1 = sa1 >> 1;
        float sc0 = (sa0 & 1) ? s1 : s0;
        float sc1 = (sa1 & 1) ? s1 : s0;
        const float4* r0 = (const float4*)((n0 < N_USERS) ? (ue + n0*DIM) : (ie + (n0-N_USERS)*DIM));
        const float4* r1 = (const float4*)((n1 < N_USERS) ? (ue + n1*DIM) : (ie + (n1-N_USERS)*DIM));
        float4 v0 = __ldg(r0 + lane);
        float4 v1 = __ldg(r1 + lane);
        acc.x += sc0*v0.x + sc1*v1.x;
        acc.y += sc0*v0.y + sc1*v1.y;
        acc.z += sc0*v0.z + sc1*v1.z;
        acc.w += sc0*v0.w + sc1*v1.w;
        c += sc0 + sc1;
    }
    if (i < m) {
        int sa0 = g_csr[st + i];
        int n0 = sa0 >> 1;
        float sc0 = (sa0 & 1) ? s1 : s0;
        const float4* r0 = (const float4*)((n0 < N_USERS) ? (ue + n0*DIM) : (ie + (n0-N_USERS)*DIM));
        float4 v0 = __ldg(r0 + lane);
        acc.x += sc0*v0.x; acc.y += sc0*v0.y; acc.z += sc0*v0.z; acc.w += sc0*v0.w;
        c += sc0;
    }
    ((float4*)(g_S + n*DIM))[lane] = acc;
    if (lane == 0) g_cnt[n] = c;
}

// ===================== tf32 mma GEMMs =====================

__device__ __forceinline__ void mma_mainloop(const float* __restrict__ SrowA,
                                             const float* __restrict__ SrowB,
                                             const float* __restrict__ Wsh,
                                             int thr, int grp, float acc[8][4]) {
    uint32_t A0[16], A1[16], A2[16], A3[16];
#pragma unroll
    for (int ks = 0; ks < 16; ks++) {
        int k0 = ks*8;
        A0[ks] = __float_as_uint(SrowA[k0 + thr]);
        A1[ks] = __float_as_uint(SrowB[k0 + thr]);
        A2[ks] = __float_as_uint(SrowA[k0 + thr + 4]);
        A3[ks] = __float_as_uint(SrowB[k0 + thr + 4]);
    }
#pragma unroll
    for (int ks = 0; ks < 16; ks++) {
        const float* Wk0 = Wsh + (ks*8 + thr)*WST + grp;
        const float* Wk1 = Wk0 + 4*WST;
#pragma unroll
        for (int j = 0; j < 8; j++) {
            uint32_t b0 = __float_as_uint(Wk0[j*8]);
            uint32_t b1 = __float_as_uint(Wk1[j*8]);
            mma_tf32(acc[j], A0[ks], A1[ks], A2[ks], A3[ks], b0, b1);
        }
    }
}

__global__ void __launch_bounds__(128, 3) gr_gemm_kernel(const float* __restrict__ ue,
        const float* __restrict__ ie, const float* __restrict__ W, const float* __restrict__ b) {
    extern __shared__ float sm[];
    float* Ssh = sm;
    float* Wsh = sm + SSH_FLOATS;
    int*   nid  = (int*)(Wsh + WSH_FLOATS);
    float* caux = (float*)(nid + 64);
    int tid = threadIdx.x;
    int total = g_ncount;
    int base = blockIdx.x * 64;
    if (base >= total) return;
    int cb = blockIdx.y * 64;

    for (int idx = tid; idx < DIM*64; idx += 128) {
        int k = idx >> 6, n = idx & 63;
        Wsh[k*WST + n] = to_tf32(__ldg(&W[k*DIM + cb + n]));
    }
    if (tid < 64) {
        int r = base + tid;
        int n = (r < total) ? g_list[r] : -1;
        nid[tid] = n; caux[tid] = (n >= 0) ? g_cnt[n] : 0.f;
    }
    __syncthreads();
    int wp = tid >> 5, lane = tid & 31;
    for (int r = wp; r < 64; r += 4) {
        int n = nid[r];
        float4 v = (n >= 0) ? ((const float4*)(g_S + n*DIM))[lane] : make_float4(0,0,0,0);
        *(float4*)(Ssh + r*SST + lane*4) =
            make_float4(to_tf32(v.x), to_tf32(v.y), to_tf32(v.z), to_tf32(v.w));
    }
    __syncthreads();

    int grp = lane >> 2, thr = lane & 3;
    const float* SrowA = Ssh + (wp*16 + grp)*SST;
    const float* SrowB = SrowA + 8*SST;
    float acc[8][4];
#pragma unroll
    for (int j = 0; j < 8; j++)
#pragma unroll
        for (int q = 0; q < 4; q++) acc[j][q] = 0.f;

    mma_mainloop(SrowA, SrowB, Wsh, thr, grp, acc);

    int rA = wp*16 + grp, rB = rA + 8;
    int nA = nid[rA], nB = nid[rB];
    float cA = caux[rA], cB = caux[rB];
#pragma unroll
    for (int j = 0; j < 8; j++) {
        int col = cb + j*8 + thr*2;
        float2 bb = __ldg((const float2*)(b + col));
        if (nA >= 0) {
            const float* emb = ((nA < N_USERS) ? ue + nA*DIM : ie + (nA-N_USERS)*DIM) + col;
            float2 e = __ldg((const float2*)emb);
            float2 o;
            o.x = e.x + fmaxf(fmaf(cA, bb.x, acc[j][0]), 0.f);
            o.y = e.y + fmaxf(fmaf(cA, bb.y, acc[j][1]), 0.f);
            *(float2*)(g_GR + nA*DIM + col) = o;
        }
        if (nB >= 0) {
            const float* emb = ((nB < N_USERS) ? ue + nB*DIM : ie + (nB-N_USERS)*DIM) + col;
            float2 e = __ldg((const float2*)emb);
            float2 o;
            o.x = e.x + fmaxf(fmaf(cB, bb.x, acc[j][2]), 0.f);
            o.y = e.y + fmaxf(fmaf(cB, bb.y, acc[j][3]), 0.f);
            *(float2*)(g_GR + nB*DIM + col) = o;
        }
    }
}

__global__ void __launch_bounds__(128, 3) xw_gemm_kernel(const int* __restrict__ x_idx,
        const int* __restrict__ dl_in) {
    extern __shared__ float sm[];
    float* Ssh = sm;
    float* Wsh = sm + SSH_FLOATS;
    int* dl = (int*)(Wsh + WSH_FLOATS);
    int tid = threadIdx.x;
    int base = blockIdx.x * 64;
    int cb = blockIdx.y * 64;

    for (int idx = tid; idx < DIM*64; idx += 128) {
        int k = idx >> 6, n = idx & 63;
        Wsh[k*WST + n] = to_tf32(g_M1[k*DIM + cb + n]);
    }
    if (tid < 64) dl[tid] = dl_in[base + tid];
    __syncthreads();
    int wp = tid >> 5, lane = tid & 31;
    for (int r = wp; r < 64; r += 4) {
        int n = __ldg(&x_idx[base + r]);
        float4 v = ((const float4*)(g_GR + n*DIM))[lane];
        *(float4*)(Ssh + r*SST + lane*4) =
            make_float4(to_tf32(v.x), to_tf32(v.y), to_tf32(v.z), to_tf32(v.w));
    }
    __syncthreads();

    int grp = lane >> 2, thr = lane & 3;
    const float* SrowA = Ssh + (wp*16 + grp)*SST;
    const float* SrowB = SrowA + 8*SST;
    float acc[8][4];
#pragma unroll
    for (int j = 0; j < 8; j++)
#pragma unroll
        for (int q = 0; q < 4; q++) acc[j][q] = 0.f;

    mma_mainloop(SrowA, SrowB, Wsh, thr, grp, acc);

    int rA = wp*16 + grp, rB = rA + 8;
    const float* dpA = g_DP2 + dl[rA]*DIM;
    const float* dpB = g_DP2 + dl[rB]*DIM;
#pragma unroll
    for (int j = 0; j < 8; j++) {
        int col = cb + j*8 + thr*2;
        float2 dA = *(const float2*)(dpA + col);
        float2 dB = *(const float2*)(dpB + col);
        *(float2*)(g_XW + (base + rA)*DIM + col) =
            make_float2(acc[j][0] + dA.x, acc[j][1] + dA.y);
        *(float2*)(g_XW + (base + rB)*DIM + col) =
            make_float2(acc[j][2] + dB.x, acc[j][3] + dB.y);
    }
}

// ===================== small kernels =====================

__global__ void gather_roots_kernel(const int* __restrict__ ru, const int* __restrict__ ri,
                                    float* __restrict__ out) {
    int i = blockIdx.x*blockDim.x + threadIdx.x;
    if (i >= 2*BB*32) return;
    int row = i >> 5, lane = i & 31;
    if (row < BB) {
        int n = __ldg(&ru[row]);
        ((float4*)(out + OFF_GU + row*DIM))[lane] = ((const float4*)(g_GR + n*DIM))[lane];
    } else {
        int b = row - BB;
        int n = __ldg(&ri[b]) + N_USERS;
        ((float4*)(g_gi + b*DIM))[lane] = ((const float4*)(g_GR + n*DIM))[lane];
    }
}

__global__ void __launch_bounds__(128) intent_kernel(const float* __restrict__ emb,
        const float* __restrict__ w1, const float* __restrict__ b1,
        const float* __restrict__ w2, const float* __restrict__ b2,
        const float* __restrict__ proto, float* __restrict__ out_p, float* __restrict__ out_r) {
    __shared__ float E[16][DIM]; __shared__ float T[16][DIM]; __shared__ float P[16][KP];
    int tid = threadIdx.x;
    int b0 = blockIdx.x * 16;
    for (int t = tid; t < 16*DIM; t += 128) E[t>>7][t&127] = emb[b0*DIM + t];
    __syncthreads();
    float acc[16];
#pragma unroll
    for (int r = 0; r < 16; r++) acc[r] = 0.f;
    for (int k = 0; k < DIM; k++) {
        float w = __ldg(&w1[k*DIM + tid]);
#pragma unroll
        for (int r = 0; r < 16; r++) acc[r] = fmaf(E[r][k], w, acc[r]);
    }
    float bb1 = __ldg(&b1[tid]);
#pragma unroll
    for (int r = 0; r < 16; r++) T[r][tid] = tanhf(acc[r] + bb1);
    __syncthreads();
    {
        int r = tid >> 3, c = tid & 7;
        float lg = __ldg(&b2[c]);
        for (int k = 0; k < DIM; k++) lg = fmaf(T[r][k], __ldg(&w2[k*KP + c]), lg);
        P[r][c] = lg;
    }
    __syncthreads();
    if (tid < 16) {
        float m = -1e30f;
#pragma unroll
        for (int c = 0; c < KP; c++) m = fmaxf(m, P[tid][c]);
        float e[KP], s = 0.f;
#pragma unroll
        for (int c = 0; c < KP; c++) { e[c] = expf(P[tid][c] - m); s += e[c]; }
        float inv = 1.f / s;
#pragma unroll
        for (int c = 0; c < KP; c++) {
            float p = e[c]*inv; P[tid][c] = p;
            out_p[(b0+tid)*KP + c] = p;
        }
    }
    __syncthreads();
#pragma unroll
    for (int r = 0; r < 16; r++) {
        float a = 0.f;
#pragma unroll
        for (int c = 0; c < KP; c++) a = fmaf(P[r][c], __ldg(&proto[c*DIM + tid]), a);
        out_r[(b0+r)*DIM + tid] = a;
    }
}

__global__ void deg_kernel(const int* __restrict__ ldst) {
    int i = blockIdx.x*blockDim.x + threadIdx.x;
    if (i < ELOC) atomicAdd(&g_deg[__ldg(&ldst[i])], 1);
}
__global__ void dinv_kernel() {
    int i = blockIdx.x*blockDim.x + threadIdx.x;
    if (i < NLOC) g_dinv[i] = rsqrtf((float)(g_deg[i] + 1));
}

// local CSR range allocation (NLOC nodes)
__global__ void lstart_kernel() {
    int i = blockIdx.x*blockDim.x + threadIdx.x;
    int lane = threadIdx.x & 31;
    int s = (i < NLOC) ? g_deg[i] : 0;
    int incl = s;
#pragma unroll
    for (int o = 1; o < 32; o <<= 1) {
        int v = __shfl_up_sync(0xffffffffu, incl, o);
        if (lane >= o) incl += v;
    }
    int wsum = __shfl_sync(0xffffffffu, incl, 31);
    int base = 0;
    if (lane == 31 && wsum) base = atomicAdd(&g_ltotal, wsum);
    base = __shfl_sync(0xffffffffu, base, 31);
    if (i < NLOC) {
        int st = base + incl - s;
        g_ls[i] = st;
        g_lc[i] = st;
    }
}

__global__ void lcsr_kernel(const int* __restrict__ lsrc, const int* __restrict__ ldst) {
    int i = blockIdx.x*blockDim.x + threadIdx.x;
    if (i >= ELOC) return;
    int d = __ldg(&ldst[i]);
    int slot = atomicAdd(&g_lc[d], 1);
    g_lcsr[slot] = __ldg(&lsrc[i]);
}

// Fused: GCN accumulate (registers) + bias + pooled scatter into hsum. LO never materialized.
__global__ void lo_pool_kernel(const int* __restrict__ batch, const float* __restrict__ gcb) {
    int w = (blockIdx.x*blockDim.x + threadIdx.x) >> 5;
    int lane = threadIdx.x & 31;
    if (w >= NLOC) return;
    int n = w;
    float di = g_dinv[n];
    int st = g_ls[n];
    int m = g_deg[n];
    float4 x = ((const float4*)(g_XW + n*DIM))[lane];
    float nm_self = di*di;
    float4 acc = make_float4(nm_self*x.x, nm_self*x.y, nm_self*x.z, nm_self*x.w);
    int i = 0;
    for (; i + 1 < m; i += 2) {
        int s0 = g_lcsr[st + i], s1 = g_lcsr[st + i + 1];
        float nm0 = g_dinv[s0] * di;
        float nm1 = g_dinv[s1] * di;
        float4 v0 = __ldg(((const float4*)(g_XW + s0*DIM)) + lane);
        float4 v1 = __ldg(((const float4*)(g_XW + s1*DIM)) + lane);
        acc.x += nm0*v0.x + nm1*v1.x;
        acc.y += nm0*v0.y + nm1*v1.y;
        acc.z += nm0*v0.z + nm1*v1.z;
        acc.w += nm0*v0.w + nm1*v1.w;
    }
    if (i < m) {
        int s0 = g_lcsr[st + i];
        float nm0 = g_dinv[s0] * di;
        float4 v0 = __ldg(((const float4*)(g_XW + s0*DIM)) + lane);
        acc.x += nm0*v0.x; acc.y += nm0*v0.y; acc.z += nm0*v0.z; acc.w += nm0*v0.w;
    }
    float4 b = __ldg(((const float4*)gcb) + lane);
    int bb = __ldg(&batch[n]);
    atomic_add4(g_hsum + bb*DIM + lane*4, acc.x + b.x, acc.y + b.y, acc.z + b.z, acc.w + b.w);
    if (lane == 0) atomicAdd(&g_cntB[bb], 1.f);
}

__device__ __forceinline__ void gemm_core64(const float* __restrict__ Wsh,
                                            const float* __restrict__ Ssh,
                                            int r0, int tx4, float4 acc[8]) {
#pragma unroll 4
    for (int k = 0; k < DIM; k += 4) {
        float4 w0 = *(const float4*)(Wsh + (k+0)*64 + tx4);
        float4 w1 = *(const float4*)(Wsh + (k+1)*64 + tx4);
        float4 w2 = *(const float4*)(Wsh + (k+2)*64 + tx4);
        float4 w3 = *(const float4*)(Wsh + (k+3)*64 + tx4);
#pragma unroll
        for (int i = 0; i < 8; i++) {
            float4 s = *(const float4*)(Ssh + (r0+i)*DIM + k);
            acc[i].x = fmaf(s.w,w3.x, fmaf(s.z,w2.x, fmaf(s.y,w1.x, fmaf(s.x,w0.x, acc[i].x))));
            acc[i].y = fmaf(s.w,w3.y, fmaf(s.z,w2.y, fmaf(s.y,w1.y, fmaf(s.x,w0.y, acc[i].y))));
            acc[i].z = fmaf(s.w,w3.z, fmaf(s.z,w2.z, fmaf(s.y,w1.z, fmaf(s.x,w0.z, acc[i].z))));
            acc[i].w = fmaf(s.w,w3.w, fmaf(s.z,w2.w, fmaf(s.y,w1.w, fmaf(s.x,w0.w, acc[i].w))));
        }
    }
}

__device__ __forceinline__ void load_w64(float* Wsh, const float* __restrict__ W,
                                         int cb, int tid) {
    for (int t = tid; t < DIM*64/4; t += 128) {
        int k = t >> 4, c4 = (t & 15) * 4;
        *(float4*)(Wsh + k*64 + c4) = __ldg((const float4*)(W + k*DIM + cb + c4));
    }
}

__global__ void __launch_bounds__(128) pool_gemm_kernel(const float* __restrict__ pw,
        const float* __restrict__ pb, float* __restrict__ out_hsub) {
    extern __shared__ float sm[];
    float* Wsh = sm; float* Ssh = sm + 8192; float* caux = Ssh + 8192;
    int tid = threadIdx.x;
    int base = blockIdx.x * 64;
    int cb = blockIdx.y * 64;
    load_w64(Wsh, pw, cb, tid);
    if (tid < 64) caux[tid] = 1.f / fmaxf(g_cntB[base + tid], 1.f);
    __syncthreads();
    int wp = tid >> 5, lane = tid & 31;
    for (int r = wp; r < 64; r += 4) {
        float sc = caux[r];
        float4 v = ((const float4*)(g_hsum + (base + r)*DIM))[lane];
        ((float4*)(Ssh + r*DIM))[lane] = make_float4(sc*v.x, sc*v.y, sc*v.z, sc*v.w);
    }
    __syncthreads();
    int ty = tid >> 4, tx = tid & 15, r0 = ty*8, tx4 = tx*4;
    int jg = cb + tx4;
    float4 acc[8];
#pragma unroll
    for (int i = 0; i < 8; i++) acc[i] = make_float4(0.f,0.f,0.f,0.f);
    gemm_core64(Wsh, Ssh, r0, tx4, acc);
    float4 bb = __ldg((const float4*)(pb + jg));
#pragma unroll
    for (int i = 0; i < 8; i++) {
        *(float4*)(out_hsub + (base + r0 + i)*DIM + jg) =
            make_float4(tanhf(acc[i].x+bb.x), tanhf(acc[i].y+bb.y),
                        tanhf(acc[i].z+bb.z), tanhf(acc[i].w+bb.w));
    }
}

__global__ void __launch_bounds__(256) final_kernel(const float* __restrict__ w1,
        const float* __restrict__ b1, const float* __restrict__ w2,
        const float* __restrict__ b2, float* __restrict__ out) {
    __shared__ float FV[4][4*DIM]; __shared__ float H[4][64];
    int tid = threadIdx.x;
    int b0 = blockIdx.x * 4;
    for (int t = tid; t < 4*512; t += 256) {
        int r = t >> 9, k = t & 511;
        int b = b0 + r;
        float v;
        if (k < 128)      v = out[OFF_HSUB + b*DIM + k];
        else if (k < 256) v = out[OFF_GU + b*DIM + (k-128)];
        else if (k < 384) v = g_gi[b*DIM + (k-256)];
        else              v = g_ru[b*DIM + (k-384)] * g_rv[b*DIM + (k-384)];
        FV[r][k] = v;
    }
    __syncthreads();
    int r = tid >> 6, h = tid & 63;
    float acc = __ldg(&b1[h]);
    for (int k = 0; k < 512; k++) acc = fmaf(FV[r][k], __ldg(&w1[k*64 + h]), acc);
    H[r][h] = fmaxf(acc, 0.f);
    __syncthreads();
    if (tid < 4) {
        float a = __ldg(&b2[0]);
        for (int h2 = 0; h2 < 64; h2++) a = fmaf(H[tid][h2], __ldg(&w2[h2]), a);
        out[OFF_PRED + b0 + tid] = 1.f / (1.f + expf(-a));
    }
}

namespace {
struct EagerInit {
    EagerInit() {
        void* p;
        cudaGetSymbolAddress(&p, g_S);
        cudaFuncAttributes fa;
        cudaFuncGetAttributes(&fa, precompute_kernel);
        cudaFuncGetAttributes(&fa, mark_kernel);
        cudaFuncGetAttributes(&fa, edge_compact_kernel);
        cudaFuncGetAttributes(&fa, start_kernel);
        cudaFuncGetAttributes(&fa, csr_scatter_kernel);
        cudaFuncGetAttributes(&fa, edge_scatter3_kernel);
        cudaFuncGetAttributes(&fa, gr_gemm_kernel);
        cudaFuncGetAttributes(&fa, xw_gemm_kernel);
        cudaFuncGetAttributes(&fa, gather_roots_kernel);
        cudaFuncGetAttributes(&fa, intent_kernel);
        cudaFuncGetAttributes(&fa, deg_kernel);
        cudaFuncGetAttributes(&fa, dinv_kernel);
        cudaFuncGetAttributes(&fa, lstart_kernel);
        cudaFuncGetAttributes(&fa, lcsr_kernel);
        cudaFuncGetAttributes(&fa, lo_pool_kernel);
        cudaFuncGetAttributes(&fa, pool_gemm_kernel);
        cudaFuncGetAttributes(&fa, final_kernel);
        cudaFuncSetAttribute(gr_gemm_kernel,   cudaFuncAttributeMaxDynamicSharedMemorySize, GSMEM3);
        cudaFuncSetAttribute(xw_gemm_kernel,   cudaFuncAttributeMaxDynamicSharedMemorySize, GSMEM3);
        cudaFuncSetAttribute(pool_gemm_kernel, cudaFuncAttributeMaxDynamicSharedMemorySize, GSMEM2);
    }
};
EagerInit _eager_init;
}

extern "C" void kernel_launch(void* const* d_in, const int* in_sizes, int n_in,
                              void* d_out, int out_size) {
    const int *gei = (const int*)d_in[0], *gea = (const int*)d_in[1];
    const int *root_u = (const int*)d_in[2], *root_i = (const int*)d_in[3];
    const int *x_idx = (const int*)d_in[4], *dist_label = (const int*)d_in[5];
    const int *lei = (const int*)d_in[6], *batch = (const int*)d_in[7];
    const float *ue = (const float*)d_in[8], *ie = (const float*)d_in[9];
    const float *demb = (const float*)d_in[10];
    const float *c_u = (const float*)d_in[11], *c_v = (const float*)d_in[12];
    const float *gnn_W = (const float*)d_in[13], *gnn_b = (const float*)d_in[14];
    const float *sign_emb = (const float*)d_in[15];
    const float *iw1 = (const float*)d_in[16], *ib1 = (const float*)d_in[17];
    const float *iw2 = (const float*)d_in[18], *ib2 = (const float*)d_in[19];
    const float *lpw = (const float*)d_in[20], *lpb = (const float*)d_in[21];
    const float *gcw = (const float*)d_in[22], *gcb = (const float*)d_in[23];
    const float *pw = (const float*)d_in[24], *pb = (const float*)d_in[25];
    const float *fw1 = (const float*)d_in[26], *fb1 = (const float*)d_in[27];
    const float *fw2 = (const float*)d_in[28], *fb2 = (const float*)d_in[29];
    float* out = (float*)d_out;
    const int *gsrc = gei, *gdst = gei + EG;
    const int *lsrc = lei, *ldst = lei + ELOC;

    void *pMask, *pNc, *pEc, *pEt, *pLt, *pDeg, *pHsum, *pCntB, *pGi, *pRu, *pRv;
    cudaGetSymbolAddress(&pMask, g_mask);
    cudaGetSymbolAddress(&pNc, g_ncount);
    cudaGetSymbolAddress(&pEc, g_ecount);
    cudaGetSymbolAddress(&pEt, g_etotal);
    cudaGetSymbolAddress(&pLt, g_ltotal);
    cudaGetSymbolAddress(&pDeg, g_deg);
    cudaGetSymbolAddress(&pHsum, g_hsum);
    cudaGetSymbolAddress(&pCntB, g_cntB);
    cudaGetSymbolAddress(&pGi, g_gi);
    cudaGetSymbolAddress(&pRu, g_ru);
    cudaGetSymbolAddress(&pRv, g_rv);

    cudaMemsetAsync(pMask, 0, NTOT*4);
    cudaMemsetAsync(pNc, 0, 4);
    cudaMemsetAsync(pEc, 0, 4);
    cudaMemsetAsync(pEt, 0, 4);
    cudaMemsetAsync(pLt, 0, 4);
    cudaMemsetAsync(pDeg, 0, NLOC*4);
    cudaMemsetAsync(pHsum, 0, BB*DIM*4);
    cudaMemsetAsync(pCntB, 0, BB*4);

    precompute_kernel<<<DIM+4, 128>>>(lpw, lpb, gcw, demb);
    mark_kernel<<<MAXNEED/256, 256>>>(x_idx, root_u, root_i);
    edge_compact_kernel<<<(EG + 256*ECPT - 1)/(256*ECPT), 256>>>(gsrc, gdst, gea);
    start_kernel<<<(MAXNEED+255)/256, 256>>>();
    csr_scatter_kernel<<<(EG+255)/256, 256>>>();
    edge_scatter3_kernel<<<MAXNEED*32/256, 256>>>(ue, ie, sign_emb);
    gr_gemm_kernel<<<dim3(MAXNEED/64, 2), 128, GSMEM3>>>(ue, ie, gnn_W, gnn_b);
    gather_roots_kernel<<<(2*BB*32+255)/256, 256>>>(root_u, root_i, out);
    intent_kernel<<<BB/16, 128>>>(out + OFF_GU, iw1, ib1, iw2, ib2, c_u,
                                  out + OFF_PU, (float*)pRu);
    intent_kernel<<<BB/16, 128>>>((const float*)pGi, iw1, ib1, iw2, ib2, c_v,
                                  out + OFF_PV, (float*)pRv);
    xw_gemm_kernel<<<dim3(NLOC/64, 2), 128, GSMEM3>>>(x_idx, dist_label);
    deg_kernel<<<(ELOC+255)/256, 256>>>(ldst);
    dinv_kernel<<<(NLOC+255)/256, 256>>>();
    lstart_kernel<<<(NLOC+255)/256, 256>>>();
    lcsr_kernel<<<(ELOC+255)/256, 256>>>(lsrc, ldst);
    lo_pool_kernel<<<NLOC*32/256, 256>>>(batch, gcb);
    pool_gemm_kernel<<<dim3(BB/64, 2), 128, GSMEM2>>>(pw, pb, out + OFF_HSUB);
    final_kernel<<<BB/4, 256>>>(fw1, fb1, fw2, fb2, out);
}